// round 14
// baseline (speedup 1.0000x reference)
#include <cuda_runtime.h>
#include <cuda_bf16.h>
#include <cuda_fp16.h>
#include <math.h>
#include <cstdint>

#define Bc 8
#define N1c 4096
#define N2c 2048
#define Hc 64
#define Kc 8
#define CH 8    // candidate chunks per kNN pass
#define RC 16   // rescored candidates per query

// ---------------- device scratch (no cudaMalloc allowed) ----------------
__device__ float    g_h1 [Bc*N1c*Hc];
__device__ float    g_x2a[Bc*N1c];
__device__ int      g_nbr1[Bc*N1c*Kc];
__device__ float    g_Pd1[Bc*N1c*96];
__device__ float    g_Ps1[Bc*N1c*96];
__device__ unsigned g_agg1[Bc*N1c*Hc];
__device__ float    g_h3 [Bc*N2c*Hc];
__device__ float    g_x2b[Bc*N2c];
__device__ int      g_nbr2[Bc*N2c*Kc];
__device__ float    g_Pd2[Bc*N2c*96];
__device__ float    g_Ps2[Bc*N2c*96];
__device__ unsigned g_agg2[Bc*N2c*Hc];
__device__ float    g_pd1[Bc*N1c*CH*Kc];
__device__ int      g_pi1[Bc*N1c*CH*Kc];
__device__ float    g_pd2[Bc*N2c*CH*Kc];
__device__ int      g_pi2[Bc*N2c*CH*Kc];
__device__ int      g_cand1[Bc*N1c*RC];
__device__ int      g_cand2[Bc*N2c*RC];
__device__ __half   g_hq1[Bc*N1c*Hc];
__device__ __half   g_hq2[Bc*N2c*Hc];

// ---------------- helpers ----------------
__device__ __forceinline__ float eluf(float x) { return x > 0.f ? x : expm1f(x); }

__device__ __forceinline__ unsigned encf(float f) {
    unsigned u = __float_as_uint(f);
    return (u & 0x80000000u) ? ~u : (u | 0x80000000u);
}
__device__ __forceinline__ float decf(unsigned u) {
    return __uint_as_float((u & 0x80000000u) ? (u ^ 0x80000000u) : ~u);
}

__device__ __forceinline__ void ldm4(unsigned* r, unsigned addr) {
    asm volatile("ldmatrix.sync.aligned.m8n8.x4.shared.b16 {%0,%1,%2,%3},[%4];"
                 : "=r"(r[0]), "=r"(r[1]), "=r"(r[2]), "=r"(r[3]) : "r"(addr));
}
__device__ __forceinline__ void ldm2(unsigned* r, unsigned addr) {
    asm volatile("ldmatrix.sync.aligned.m8n8.x2.shared.b16 {%0,%1},[%2];"
                 : "=r"(r[0]), "=r"(r[1]) : "r"(addr));
}
__device__ __forceinline__ void mma16816h(float* c, const unsigned* a, const unsigned* b) {
    asm volatile("mma.sync.aligned.m16n8k16.row.col.f32.f16.f16.f32 "
                 "{%0,%1,%2,%3},{%4,%5,%6,%7},{%8,%9},{%0,%1,%2,%3};"
                 : "+f"(c[0]), "+f"(c[1]), "+f"(c[2]), "+f"(c[3])
                 : "r"(a[0]), "r"(a[1]), "r"(a[2]), "r"(a[3]), "r"(b[0]), "r"(b[1]));
}

// ---------------- zero both agg arrays in ONE launch ----------------
__global__ void zero2_kernel(unsigned* a, int na, unsigned* b, int nb) {
    for (int i = blockIdx.x * blockDim.x + threadIdx.x; i < na; i += gridDim.x * blockDim.x)
        a[i] = 0u;
    for (int i = blockIdx.x * blockDim.x + threadIdx.x; i < nb; i += gridDim.x * blockDim.x)
        b[i] = 0u;
}

__global__ void half_kernel(const float* __restrict__ in, __half* __restrict__ o, int n) {
    int i = blockIdx.x * blockDim.x + threadIdx.x;
    if (i < n) o[i] = __float2half(in[i]);
}

// ---------------- input MLP ----------------
__global__ void input_mlp_kernel(const float* __restrict__ x, const float* __restrict__ nrm,
                                 const float* __restrict__ w1, const float* __restrict__ b1,
                                 const float* __restrict__ w2, const float* __restrict__ b2,
                                 float* __restrict__ h, float* __restrict__ x2) {
    __shared__ float sw1[10 * 32], sb1[32], sw2[32 * 64], sb2[64], snrm[10];
    for (int idx = threadIdx.x; idx < 320; idx += blockDim.x) sw1[idx] = w1[idx];
    for (int idx = threadIdx.x; idx < 2048; idx += blockDim.x) sw2[idx] = w2[idx];
    if (threadIdx.x < 32) sb1[threadIdx.x] = b1[threadIdx.x];
    if (threadIdx.x < 64) sb2[threadIdx.x] = b2[threadIdx.x];
    if (threadIdx.x < 10) snrm[threadIdx.x] = nrm[threadIdx.x];
    __syncthreads();
    int n = blockIdx.x * blockDim.x + threadIdx.x;
    float xv[10];
#pragma unroll
    for (int c = 0; c < 10; c++) xv[c] = x[n * 10 + c] * snrm[c];
    float a[32];
#pragma unroll
    for (int o = 0; o < 32; o++) {
        float acc = sb1[o];
#pragma unroll
        for (int c = 0; c < 10; c++) acc = fmaf(xv[c], sw1[c * 32 + o], acc);
        a[o] = eluf(acc);
    }
    float ss = 0.f;
#pragma unroll 4
    for (int o = 0; o < 64; o++) {
        float acc = sb2[o];
#pragma unroll
        for (int c = 0; c < 32; c++) acc = fmaf(a[c], sw2[c * 64 + o], acc);
        acc = eluf(acc);
        h[(size_t)n * 64 + o] = acc;
        ss = fmaf(acc, acc, ss);
    }
    x2[n] = ss;
}

// ---------------- fp16 screen kNN: fused scan, group-of-4 threshold test ----------------
#define SM_Q 0
#define SM_C 9216
#define SM_X2M 27648
#define KNN_SMEM 28160
#define TS 144

template <int N>
__global__ void __launch_bounds__(128, 4) knn_screen_kernel(
    const __half* __restrict__ hq, const float* __restrict__ x2,
    float* __restrict__ part_d, int* __restrict__ part_i) {
    extern __shared__ unsigned char sm_raw[];
    const unsigned sb = (unsigned)__cvta_generic_to_shared(sm_raw);
    const int b = blockIdx.z, ch = blockIdx.y;
    const int i0 = blockIdx.x * 64;
    const int tid = threadIdx.x, lane = tid & 31, w = tid >> 5;
    const int j0 = ch * (N / CH), j1 = j0 + (N / CH);
    const __half* hb = hq + (size_t)b * N * 64;

    for (int idx = tid; idx < 64 * 8; idx += 128) {
        int r = idx >> 3, c = idx & 7;
        *(uint4*)(sm_raw + SM_Q + r * TS + c * 16) = *(const uint4*)(hb + (size_t)(i0 + r) * 64 + c * 8);
    }

    const int sub = lane >> 3, l7 = lane & 7;
    const int r0 = 16 * w + (lane >> 2);
    const int q0 = i0 + r0, q1 = q0 + 8;
    const float x2q0 = x2[b * N + q0];
    const float x2q1 = x2[b * N + q1];
    const int dcol = (lane & 3) * 2;

    float bd0[8], bd1[8]; int bi0[8], bi1[8];
#pragma unroll
    for (int r = 0; r < 8; r++) { bd0[r] = 3e38f; bi0[r] = 0; bd1[r] = 3e38f; bi1[r] = 0; }

    const int arow = 16 * w + l7 + ((sub & 1) ? 8 : 0);
    const unsigned aoff = (unsigned)(arow * TS + ((sub >> 1) ? 16 : 0));
    const unsigned boff = (unsigned)(l7 * TS + (((lane >> 3) & 1) ? 16 : 0));

    for (int jt = j0; jt < j1; jt += 128) {
        for (int idx = tid; idx < 128 * 8; idx += 128) {
            int r = idx >> 3, c = idx & 7;
            *(uint4*)(sm_raw + SM_C + r * TS + c * 16) = *(const uint4*)(hb + (size_t)(jt + r) * 64 + c * 8);
        }
        ((float*)(sm_raw + SM_X2M))[tid] = -0.5f * x2[b * N + jt + tid];
        __syncthreads();

#pragma unroll 1
        for (int half = 0; half < 2; half++) {
            const int ntb = half * 8;
            float acc[8][4];
#pragma unroll
            for (int nt = 0; nt < 8; nt++) {
                float2 v = *(const float2*)(sm_raw + SM_X2M + (8 * (ntb + nt) + dcol) * 4);
                acc[nt][0] = v.x; acc[nt][1] = v.y;
                acc[nt][2] = v.x; acc[nt][3] = v.y;
            }
#pragma unroll 1
            for (int ks = 0; ks < 4; ks++) {
                unsigned ah[4];
                ldm4(ah, sb + SM_Q + aoff + ks * 32);
                unsigned bah = sb + SM_C + boff + (unsigned)(ntb * 8 * TS) + ks * 32;
#pragma unroll
                for (int nt = 0; nt < 8; nt++) {
                    unsigned bh[2];
                    ldm2(bh, bah);
                    mma16816h(acc[nt], ah, bh);
                    bah += 8 * TS;
                }
            }
            // grouped scan: 4 candidates per threshold test, no self check (filtered at rescore)
#pragma unroll
            for (int nt = 0; nt < 8; nt += 2) {
                const int jb = jt + 8 * (ntb + nt) + dcol;
                // row 0
                {
                    float da = fmaf(-2.f, acc[nt][0], x2q0);
                    float db = fmaf(-2.f, acc[nt][1], x2q0);
                    float dc = fmaf(-2.f, acc[nt + 1][0], x2q0);
                    float dd = fmaf(-2.f, acc[nt + 1][1], x2q0);
                    float mn = fminf(fminf(da, db), fminf(dc, dd));
                    if (mn < bd0[7]) {
                        float dv[4] = {da, db, dc, dd};
                        int jv[4] = {jb, jb + 1, jb + 8, jb + 9};
#pragma unroll
                        for (int u = 0; u < 4; u++) {
                            if (dv[u] < bd0[7]) {
                                bd0[7] = dv[u]; bi0[7] = jv[u];
#pragma unroll
                                for (int r = 7; r > 0; --r) {
                                    if (bd0[r] < bd0[r - 1]) {
                                        float tb = bd0[r]; bd0[r] = bd0[r - 1]; bd0[r - 1] = tb;
                                        int ti = bi0[r]; bi0[r] = bi0[r - 1]; bi0[r - 1] = ti;
                                    }
                                }
                            }
                        }
                    }
                }
                // row 1
                {
                    float da = fmaf(-2.f, acc[nt][2], x2q1);
                    float db = fmaf(-2.f, acc[nt][3], x2q1);
                    float dc = fmaf(-2.f, acc[nt + 1][2], x2q1);
                    float dd = fmaf(-2.f, acc[nt + 1][3], x2q1);
                    float mn = fminf(fminf(da, db), fminf(dc, dd));
                    if (mn < bd1[7]) {
                        float dv[4] = {da, db, dc, dd};
                        int jv[4] = {jb, jb + 1, jb + 8, jb + 9};
#pragma unroll
                        for (int u = 0; u < 4; u++) {
                            if (dv[u] < bd1[7]) {
                                bd1[7] = dv[u]; bi1[7] = jv[u];
#pragma unroll
                                for (int r = 7; r > 0; --r) {
                                    if (bd1[r] < bd1[r - 1]) {
                                        float tb = bd1[r]; bd1[r] = bd1[r - 1]; bd1[r - 1] = tb;
                                        int ti = bi1[r]; bi1[r] = bi1[r - 1]; bi1[r - 1] = ti;
                                    }
                                }
                            }
                        }
                    }
                }
            }
        }
        __syncthreads();
    }

    // stage 4 partial lists per query row, then 4-way lexicographic merge
    {
        float* stg = (float*)(sm_raw + SM_C);
        const int slot = lane & 3;
        float* dst0 = stg + (r0 * 4 + slot) * 16;
        float* dst1 = stg + ((r0 + 8) * 4 + slot) * 16;
#pragma unroll
        for (int r = 0; r < 8; r++) {
            dst0[r] = bd0[r]; ((int*)dst0)[8 + r] = bi0[r];
            dst1[r] = bd1[r]; ((int*)dst1)[8 + r] = bi1[r];
        }
    }
    __syncthreads();
    if (tid < 64) {
        const float* qs = (const float*)(sm_raw + SM_C) + tid * 64;
        size_t base = (((size_t)(b * N + i0 + tid)) * CH + ch) * 8;
        int p[4] = {0, 0, 0, 0};
#pragma unroll
        for (int r = 0; r < 8; r++) {
            float bdv = 3.1e38f; int biv = 0x7fffffff; int bl = 0;
#pragma unroll
            for (int l = 0; l < 4; l++) {
                float dv = qs[l * 16 + (p[l] & 7)];
                int iv = ((const int*)qs)[l * 16 + 8 + (p[l] & 7)];
                bool ok = (p[l] < 8) && ((dv < bdv) || (dv == bdv && iv < biv));
                if (ok) { bdv = dv; biv = iv; bl = l; }
            }
            p[bl]++;
            part_d[base + r] = bdv;
            part_i[base + r] = biv;
        }
    }
}

// ---------------- select: merge CH sorted 8-lists -> RC=16 candidates ----------------
__global__ void knn_sel_kernel(const float* __restrict__ part_d, const int* __restrict__ part_i,
                               int* __restrict__ cand, int NB) {
    int q = blockIdx.x * blockDim.x + threadIdx.x;
    if (q >= NB) return;
    size_t base = (size_t)q * CH * 8;
    int p[CH];
#pragma unroll
    for (int l = 0; l < CH; l++) p[l] = 0;
#pragma unroll
    for (int r = 0; r < RC; r++) {
        float bdv = 3.1e38f; int biv = 0x7fffffff; int bl = 0;
#pragma unroll
        for (int l = 0; l < CH; l++) {
            float dv = part_d[base + l * 8 + (p[l] & 7)];
            int iv = part_i[base + l * 8 + (p[l] & 7)];
            bool ok = (p[l] < 8) && ((dv < bdv) || (dv == bdv && iv < biv));
            if (ok) { bdv = dv; biv = iv; bl = l; }
        }
        p[bl]++;
        cand[(size_t)q * RC + r] = biv;
    }
}

// ---------------- rescore: exact fp32 distance, self filtered -> top-8 ----------------
__global__ void __launch_bounds__(128) knn_rescore_kernel(
    const float* __restrict__ h, const float* __restrict__ x2,
    const int* __restrict__ cand, int* __restrict__ nbr, int N) {
    __shared__ float sd[8][RC];
    __shared__ int si[8][RC];
    const int qg = blockIdx.x * 8 + (threadIdx.x >> 4);
    const int t = threadIdx.x & 15;
    const int qq = threadIdx.x >> 4;
    const int b = qg / N;
    const float* hb = h + (size_t)b * N * 64;
    const int iq = qg - b * N;
    int j = cand[(size_t)qg * RC + t];
    const float* hi = hb + (size_t)iq * 64;
    const float* hj = hb + (size_t)j * 64;
    float a0 = 0.f, a1 = 0.f, a2 = 0.f, a3 = 0.f;
#pragma unroll
    for (int c = 0; c < 64; c += 4) {
        a0 = fmaf(hi[c + 0], hj[c + 0], a0);
        a1 = fmaf(hi[c + 1], hj[c + 1], a1);
        a2 = fmaf(hi[c + 2], hj[c + 2], a2);
        a3 = fmaf(hi[c + 3], hj[c + 3], a3);
    }
    float d = x2[qg] + x2[b * N + j] - 2.f * ((a0 + a1) + (a2 + a3));
    if (j == iq) d = 3.2e38f;   // self excluded here (screen no longer filters it)
    sd[qq][t] = d;
    si[qq][t] = j;
    __syncwarp();
    if (t == 0) {
        float bd[8]; int bi[8];
#pragma unroll
        for (int r = 0; r < 8; r++) { bd[r] = 3e38f; bi[r] = 0x7fffffff; }
#pragma unroll
        for (int c = 0; c < RC; c++) {
            float dv = sd[qq][c]; int iv = si[qq][c];
            bool ins = (dv < bd[7]) || (dv == bd[7] && iv < bi[7]);
            if (ins) {
                bd[7] = dv; bi[7] = iv;
#pragma unroll
                for (int r = 7; r > 0; --r) {
                    if (bd[r] < bd[r - 1] || (bd[r] == bd[r - 1] && bi[r] < bi[r - 1])) {
                        float tb = bd[r]; bd[r] = bd[r - 1]; bd[r - 1] = tb;
                        int ti = bi[r]; bi[r] = bi[r - 1]; bi[r - 1] = ti;
                    }
                }
            }
        }
#pragma unroll
        for (int r = 0; r < 8; r++) nbr[(size_t)qg * 8 + r] = bi[r];
    }
}

// ---------------- per-node projections for EdgeConv decomposition ----------------
__global__ void proj_kernel(const float* __restrict__ h, const float* __restrict__ wa,
                            float* __restrict__ Pd, float* __restrict__ Ps, int NB) {
    __shared__ float Wd[64 * 96];
    __shared__ float Ws[64 * 96];
    for (int idx = threadIdx.x; idx < 64 * 96; idx += blockDim.x) {
        float top = wa[idx];
        float bot = wa[64 * 96 + idx];
        Wd[idx] = top - bot;
        Ws[idx] = bot;
    }
    __syncthreads();
    int warp = (blockIdx.x * blockDim.x + threadIdx.x) >> 5;
    int lane = threadIdx.x & 31;
    int nwarps = (gridDim.x * blockDim.x) >> 5;
    for (int n = warp; n < NB; n += nwarps) {
        float h0 = h[(size_t)n * 64 + lane];
        float h1 = h[(size_t)n * 64 + 32 + lane];
        float d0 = 0, d1 = 0, d2 = 0, s0 = 0, s1 = 0, s2 = 0;
#pragma unroll
        for (int c = 0; c < 64; c++) {
            float hc = __shfl_sync(0xffffffffu, (c < 32) ? h0 : h1, c & 31);
            const float* wd = &Wd[c * 96 + lane];
            const float* ws = &Ws[c * 96 + lane];
            d0 = fmaf(hc, wd[0], d0);  d1 = fmaf(hc, wd[32], d1);  d2 = fmaf(hc, wd[64], d2);
            s0 = fmaf(hc, ws[0], s0);  s1 = fmaf(hc, ws[32], s1);  s2 = fmaf(hc, ws[64], s2);
        }
        Pd[(size_t)n * 96 + lane] = d0; Pd[(size_t)n * 96 + lane + 32] = d1; Pd[(size_t)n * 96 + lane + 64] = d2;
        Ps[(size_t)n * 96 + lane] = s0; Ps[(size_t)n * 96 + lane + 32] = s1; Ps[(size_t)n * 96 + lane + 64] = s2;
    }
}

// ---------------- EdgeConv: register-blocked ----------------
#define EC_SMEM (96*32*8 + 8*2*96*8*4)
__global__ void __launch_bounds__(256, 2) edgeconv_kernel(
    const float* __restrict__ Pd, const float* __restrict__ Ps,
    const float* __restrict__ b1, const float* __restrict__ w2,
    const float* __restrict__ b2, const int* __restrict__ nbr,
    unsigned* __restrict__ agg, int Nn) {
    extern __shared__ unsigned char ec_sm[];
    float2* sW2 = (float2*)ec_sm;
    float*  sHidBase = (float*)(ec_sm + 96 * 32 * 8);

    for (int idx = threadIdx.x; idx < 96 * 32; idx += 256)
        sW2[idx] = ((const float2*)w2)[idx];

    const int w = threadIdx.x >> 5, lane = threadIdx.x & 31;
    const int gn = blockIdx.x * 8 + w;
    const int b = gn / Nn;
    float* sF = sHidBase + (size_t)w * 2 * 96 * 8;
    float* sR = sF + 96 * 8;

    const float* pdi_p = Pd + (size_t)gn * 96;
    const float* psi_p = Ps + (size_t)gn * 96;
    float pdi0 = pdi_p[lane], pdi1 = pdi_p[lane + 32], pdi2 = pdi_p[lane + 64];
    float psi0 = psi_p[lane], psi1 = psi_p[lane + 32], psi2 = psi_p[lane + 64];
    float b10 = b1[lane], b11 = b1[lane + 32], b12 = b1[lane + 64];

    int jn[8];
#pragma unroll
    for (int k = 0; k < 8; k++) jn[k] = nbr[(size_t)gn * 8 + k];

#pragma unroll 1
    for (int k = 0; k < 8; k++) {
        size_t jg = (size_t)b * Nn + jn[k];
        const float* pdj = Pd + jg * 96;
        const float* psj = Ps + jg * 96;
        float pj0 = pdj[lane], pj1 = pdj[lane + 32], pj2 = pdj[lane + 64];
        float sj0 = psj[lane], sj1 = psj[lane + 32], sj2 = psj[lane + 64];
        sF[lane * 8 + k]        = eluf(pdi0 + sj0 + b10);
        sF[(lane + 32) * 8 + k] = eluf(pdi1 + sj1 + b11);
        sF[(lane + 64) * 8 + k] = eluf(pdi2 + sj2 + b12);
        sR[lane * 8 + k]        = eluf(pj0 + psi0 + b10);
        sR[(lane + 32) * 8 + k] = eluf(pj1 + psi1 + b11);
        sR[(lane + 64) * 8 + k] = eluf(pj2 + psi2 + b12);
    }
    __syncthreads();

    float aF[8][2], aR[8][2];
#pragma unroll
    for (int e = 0; e < 8; e++) { aF[e][0] = aF[e][1] = aR[e][0] = aR[e][1] = 0.f; }

#pragma unroll 4
    for (int hh = 0; hh < 96; hh++) {
        float2 wv = sW2[hh * 32 + lane];
        float4 f03 = *(const float4*)&sF[hh * 8];
        float4 f47 = *(const float4*)&sF[hh * 8 + 4];
        float4 r03 = *(const float4*)&sR[hh * 8];
        float4 r47 = *(const float4*)&sR[hh * 8 + 4];
        aF[0][0] = fmaf(f03.x, wv.x, aF[0][0]); aF[0][1] = fmaf(f03.x, wv.y, aF[0][1]);
        aF[1][0] = fmaf(f03.y, wv.x, aF[1][0]); aF[1][1] = fmaf(f03.y, wv.y, aF[1][1]);
        aF[2][0] = fmaf(f03.z, wv.x, aF[2][0]); aF[2][1] = fmaf(f03.z, wv.y, aF[2][1]);
        aF[3][0] = fmaf(f03.w, wv.x, aF[3][0]); aF[3][1] = fmaf(f03.w, wv.y, aF[3][1]);
        aF[4][0] = fmaf(f47.x, wv.x, aF[4][0]); aF[4][1] = fmaf(f47.x, wv.y, aF[4][1]);
        aF[5][0] = fmaf(f47.y, wv.x, aF[5][0]); aF[5][1] = fmaf(f47.y, wv.y, aF[5][1]);
        aF[6][0] = fmaf(f47.z, wv.x, aF[6][0]); aF[6][1] = fmaf(f47.z, wv.y, aF[6][1]);
        aF[7][0] = fmaf(f47.w, wv.x, aF[7][0]); aF[7][1] = fmaf(f47.w, wv.y, aF[7][1]);
        aR[0][0] = fmaf(r03.x, wv.x, aR[0][0]); aR[0][1] = fmaf(r03.x, wv.y, aR[0][1]);
        aR[1][0] = fmaf(r03.y, wv.x, aR[1][0]); aR[1][1] = fmaf(r03.y, wv.y, aR[1][1]);
        aR[2][0] = fmaf(r03.z, wv.x, aR[2][0]); aR[2][1] = fmaf(r03.z, wv.y, aR[2][1]);
        aR[3][0] = fmaf(r03.w, wv.x, aR[3][0]); aR[3][1] = fmaf(r03.w, wv.y, aR[3][1]);
        aR[4][0] = fmaf(r47.x, wv.x, aR[4][0]); aR[4][1] = fmaf(r47.x, wv.y, aR[4][1]);
        aR[5][0] = fmaf(r47.y, wv.x, aR[5][0]); aR[5][1] = fmaf(r47.y, wv.y, aR[5][1]);
        aR[6][0] = fmaf(r47.z, wv.x, aR[6][0]); aR[6][1] = fmaf(r47.z, wv.y, aR[6][1]);
        aR[7][0] = fmaf(r47.w, wv.x, aR[7][0]); aR[7][1] = fmaf(r47.w, wv.y, aR[7][1]);
    }

    const float bo0 = b2[2 * lane], bo1 = b2[2 * lane + 1];
    unsigned fm0 = 0u, fm1 = 0u;
#pragma unroll
    for (int e = 0; e < 8; e++) {
        fm0 = max(fm0, encf(eluf(aF[e][0] + bo0)));
        fm1 = max(fm1, encf(eluf(aF[e][1] + bo1)));
    }
    atomicMax(agg + (size_t)gn * 64 + 2 * lane,     fm0);
    atomicMax(agg + (size_t)gn * 64 + 2 * lane + 1, fm1);
#pragma unroll
    for (int e = 0; e < 8; e++) {
        size_t jg = (size_t)b * Nn + jn[e];
        atomicMax(agg + jg * 64 + 2 * lane,     encf(eluf(aR[e][0] + bo0)));
        atomicMax(agg + jg * 64 + 2 * lane + 1, encf(eluf(aR[e][1] + bo1)));
    }
}

// ---------------- decode + pairwise max pool + sq-norm ----------------
__global__ void pool_kernel(const unsigned* __restrict__ agg, float* __restrict__ h3,
                            float* __restrict__ x2b) {
    int w = (blockIdx.x * blockDim.x + threadIdx.x) >> 5;
    int lane = threadIdx.x & 31;
    int b = w / N2c;
    int i = w - b * N2c;
    size_t s0 = ((size_t)(b * N1c + 2 * i)) * 64;
    float ss = 0.f;
#pragma unroll
    for (int r = 0; r < 2; r++) {
        int c = lane + 32 * r;
        float v = fmaxf(decf(agg[s0 + c]), decf(agg[s0 + 64 + c]));
        h3[(size_t)w * 64 + c] = v;
        ss = fmaf(v, v, ss);
    }
    for (int o = 16; o > 0; o >>= 1) ss += __shfl_down_sync(0xffffffffu, ss, o);
    if (lane == 0) x2b[w] = ss;
}

// ---------------- global max pool + head MLP ----------------
__global__ void final_kernel(const unsigned* __restrict__ agg,
                             const float* __restrict__ w1, const float* __restrict__ bb1,
                             const float* __restrict__ w2, const float* __restrict__ bb2,
                             const float* __restrict__ w3, const float* __restrict__ bb3,
                             float* __restrict__ out) {
    __shared__ float red[256];
    __shared__ float gv[64], t1[64], t2[32];
    int b = blockIdx.x;
    int c = threadIdx.x & 63, grp = threadIdx.x >> 6;
    float m = -3e38f;
    for (int n = grp; n < N2c; n += 4)
        m = fmaxf(m, decf(agg[((size_t)(b * N2c + n)) * 64 + c]));
    red[threadIdx.x] = m;
    __syncthreads();
    if (threadIdx.x < 64) {
        m = fmaxf(fmaxf(red[threadIdx.x], red[threadIdx.x + 64]),
                  fmaxf(red[threadIdx.x + 128], red[threadIdx.x + 192]));
        gv[threadIdx.x] = m;
    }
    __syncthreads();
    if (threadIdx.x < 64) {
        float acc = bb1[threadIdx.x];
#pragma unroll
        for (int cc = 0; cc < 64; cc++) acc = fmaf(gv[cc], w1[cc * 64 + threadIdx.x], acc);
        t1[threadIdx.x] = eluf(acc);
    }
    __syncthreads();
    if (threadIdx.x < 32) {
        float acc = bb2[threadIdx.x];
#pragma unroll
        for (int cc = 0; cc < 64; cc++) acc = fmaf(t1[cc], w2[cc * 32 + threadIdx.x], acc);
        t2[threadIdx.x] = eluf(acc);
    }
    __syncthreads();
    if (threadIdx.x == 0) {
        float o0 = bb3[0], o1 = bb3[1];
#pragma unroll
        for (int cc = 0; cc < 32; cc++) {
            o0 = fmaf(t2[cc], w3[cc * 2 + 0], o0);
            o1 = fmaf(t2[cc], w3[cc * 2 + 1], o1);
        }
        float met = fmaxf(o0, 0.f) + log1pf(expf(-fabsf(o0)));
        float sig = 1.f / (1.f + expf(-o1));
        float phi = 3.14159265358979323846f * (2.f * sig - 1.f);
        out[b * 2 + 0] = met;
        out[b * 2 + 1] = phi;
    }
}

// ---------------- launch ----------------
extern "C" void kernel_launch(void* const* d_in, const int* in_sizes, int n_in,
                              void* d_out, int out_size) {
    const float* x      = (const float*)d_in[0];
    const float* nrm    = (const float*)d_in[1];
    const float* w_in1  = (const float*)d_in[2];
    const float* b_in1  = (const float*)d_in[3];
    const float* w_in2  = (const float*)d_in[4];
    const float* b_in2  = (const float*)d_in[5];
    const float* w_c1a  = (const float*)d_in[6];
    const float* b_c1a  = (const float*)d_in[7];
    const float* w_c1b  = (const float*)d_in[8];
    const float* b_c1b  = (const float*)d_in[9];
    const float* w_c2a  = (const float*)d_in[10];
    const float* b_c2a  = (const float*)d_in[11];
    const float* w_c2b  = (const float*)d_in[12];
    const float* b_c2b  = (const float*)d_in[13];
    const float* w_o1   = (const float*)d_in[14];
    const float* b_o1   = (const float*)d_in[15];
    const float* w_o2   = (const float*)d_in[16];
    const float* b_o2   = (const float*)d_in[17];
    const float* w_o3   = (const float*)d_in[18];
    const float* b_o3   = (const float*)d_in[19];
    float* out = (float*)d_out;

    float *h1, *x2a, *Pd1, *Ps1, *h3, *x2b, *Pd2, *Ps2, *pd1, *pd2;
    int *nbr1, *nbr2, *pi1, *pi2, *cand1, *cand2;
    unsigned *agg1, *agg2;
    __half *hq1, *hq2;
    cudaGetSymbolAddress((void**)&h1,   g_h1);
    cudaGetSymbolAddress((void**)&x2a,  g_x2a);
    cudaGetSymbolAddress((void**)&nbr1, g_nbr1);
    cudaGetSymbolAddress((void**)&Pd1,  g_Pd1);
    cudaGetSymbolAddress((void**)&Ps1,  g_Ps1);
    cudaGetSymbolAddress((void**)&agg1, g_agg1);
    cudaGetSymbolAddress((void**)&h3,   g_h3);
    cudaGetSymbolAddress((void**)&x2b,  g_x2b);
    cudaGetSymbolAddress((void**)&nbr2, g_nbr2);
    cudaGetSymbolAddress((void**)&Pd2,  g_Pd2);
    cudaGetSymbolAddress((void**)&Ps2,  g_Ps2);
    cudaGetSymbolAddress((void**)&agg2, g_agg2);
    cudaGetSymbolAddress((void**)&pd1,  g_pd1);
    cudaGetSymbolAddress((void**)&pi1,  g_pi1);
    cudaGetSymbolAddress((void**)&pd2,  g_pd2);
    cudaGetSymbolAddress((void**)&pi2,  g_pi2);
    cudaGetSymbolAddress((void**)&cand1, g_cand1);
    cudaGetSymbolAddress((void**)&cand2, g_cand2);
    cudaGetSymbolAddress((void**)&hq1,  g_hq1);
    cudaGetSymbolAddress((void**)&hq2,  g_hq2);

    cudaFuncSetAttribute(knn_screen_kernel<N1c>, cudaFuncAttributeMaxDynamicSharedMemorySize, KNN_SMEM);
    cudaFuncSetAttribute(knn_screen_kernel<N2c>, cudaFuncAttributeMaxDynamicSharedMemorySize, KNN_SMEM);
    cudaFuncSetAttribute(edgeconv_kernel, cudaFuncAttributeMaxDynamicSharedMemorySize, EC_SMEM);

    // index 0
    zero2_kernel<<<1024, 256>>>(agg1, Bc * N1c * Hc, agg2, Bc * N2c * Hc);
    // index 1
    input_mlp_kernel<<<(Bc * N1c) / 128, 128>>>(x, nrm, w_in1, b_in1, w_in2, b_in2, h1, x2a);
    // index 2
    half_kernel<<<(Bc * N1c * Hc + 255) / 256, 256>>>(h1, hq1, Bc * N1c * Hc);
    // index 3 <-- ncu capture slot
    knn_screen_kernel<N1c><<<dim3(N1c / 64, CH, Bc), 128, KNN_SMEM>>>(hq1, x2a, pd1, pi1);
    knn_sel_kernel<<<(Bc * N1c + 255) / 256, 256>>>(pd1, pi1, cand1, Bc * N1c);
    knn_rescore_kernel<<<(Bc * N1c) / 8, 128>>>(h1, x2a, cand1, nbr1, N1c);
    proj_kernel<<<(Bc * N1c) / 8, 256>>>(h1, w_c1a, Pd1, Ps1, Bc * N1c);
    edgeconv_kernel<<<(Bc * N1c) / 8, 256, EC_SMEM>>>(Pd1, Ps1, b_c1a, w_c1b, b_c1b, nbr1, agg1, N1c);

    pool_kernel<<<(Bc * N2c) / 8, 256>>>(agg1, h3, x2b);
    half_kernel<<<(Bc * N2c * Hc + 255) / 256, 256>>>(h3, hq2, Bc * N2c * Hc);

    knn_screen_kernel<N2c><<<dim3(N2c / 64, CH, Bc), 128, KNN_SMEM>>>(hq2, x2b, pd2, pi2);
    knn_sel_kernel<<<(Bc * N2c + 255) / 256, 256>>>(pd2, pi2, cand2, Bc * N2c);
    knn_rescore_kernel<<<(Bc * N2c) / 8, 128>>>(h3, x2b, cand2, nbr2, N2c);
    proj_kernel<<<(Bc * N2c) / 8, 256>>>(h3, w_c2a, Pd2, Ps2, Bc * N2c);
    edgeconv_kernel<<<(Bc * N2c) / 8, 256, EC_SMEM>>>(Pd2, Ps2, b_c2a, w_c2b, b_c2b, nbr2, agg2, N2c);

    final_kernel<<<Bc, 256>>>(agg2, w_o1, b_o1, w_o2, b_o2, w_o3, b_o3, out);
}

// round 15
// speedup vs baseline: 1.0407x; 1.0407x over previous
#include <cuda_runtime.h>
#include <cuda_bf16.h>
#include <cuda_fp16.h>
#include <math.h>
#include <cstdint>

#define Bc 8
#define N1c 4096
#define N2c 2048
#define Hc 64
#define Kc 8
#define CH 8    // candidate chunks per kNN pass
#define RC 16   // rescored candidates per query

// ---------------- device scratch (no cudaMalloc allowed) ----------------
__device__ float    g_h1 [Bc*N1c*Hc];
__device__ float    g_x2a[Bc*N1c];
__device__ int      g_nbr1[Bc*N1c*Kc];
__device__ float    g_Pd1[Bc*N1c*96];
__device__ float    g_Ps1[Bc*N1c*96];
__device__ unsigned g_agg1[Bc*N1c*Hc];
__device__ float    g_h3 [Bc*N2c*Hc];
__device__ float    g_x2b[Bc*N2c];
__device__ int      g_nbr2[Bc*N2c*Kc];
__device__ float    g_Pd2[Bc*N2c*96];
__device__ float    g_Ps2[Bc*N2c*96];
__device__ unsigned g_agg2[Bc*N2c*Hc];
__device__ float    g_pd1[Bc*N1c*CH*Kc];
__device__ int      g_pi1[Bc*N1c*CH*Kc];
__device__ float    g_pd2[Bc*N2c*CH*Kc];
__device__ int      g_pi2[Bc*N2c*CH*Kc];
__device__ int      g_cand1[Bc*N1c*RC];
__device__ int      g_cand2[Bc*N2c*RC];
__device__ __half   g_hq1[Bc*N1c*Hc];
__device__ __half   g_hq2[Bc*N2c*Hc];

// ---------------- helpers ----------------
__device__ __forceinline__ float eluf(float x) { return x > 0.f ? x : expm1f(x); }

__device__ __forceinline__ unsigned encf(float f) {
    unsigned u = __float_as_uint(f);
    return (u & 0x80000000u) ? ~u : (u | 0x80000000u);
}
__device__ __forceinline__ float decf(unsigned u) {
    return __uint_as_float((u & 0x80000000u) ? (u ^ 0x80000000u) : ~u);
}

__device__ __forceinline__ void ldm4(unsigned* r, unsigned addr) {
    asm volatile("ldmatrix.sync.aligned.m8n8.x4.shared.b16 {%0,%1,%2,%3},[%4];"
                 : "=r"(r[0]), "=r"(r[1]), "=r"(r[2]), "=r"(r[3]) : "r"(addr));
}
__device__ __forceinline__ void ldm2(unsigned* r, unsigned addr) {
    asm volatile("ldmatrix.sync.aligned.m8n8.x2.shared.b16 {%0,%1},[%2];"
                 : "=r"(r[0]), "=r"(r[1]) : "r"(addr));
}
__device__ __forceinline__ void mma16816h(float* c, const unsigned* a, const unsigned* b) {
    asm volatile("mma.sync.aligned.m16n8k16.row.col.f32.f16.f16.f32 "
                 "{%0,%1,%2,%3},{%4,%5,%6,%7},{%8,%9},{%0,%1,%2,%3};"
                 : "+f"(c[0]), "+f"(c[1]), "+f"(c[2]), "+f"(c[3])
                 : "r"(a[0]), "r"(a[1]), "r"(a[2]), "r"(a[3]), "r"(b[0]), "r"(b[1]));
}

// ---------------- zero both agg arrays in ONE launch ----------------
__global__ void zero2_kernel(unsigned* a, int na, unsigned* b, int nb) {
    for (int i = blockIdx.x * blockDim.x + threadIdx.x; i < na; i += gridDim.x * blockDim.x)
        a[i] = 0u;
    for (int i = blockIdx.x * blockDim.x + threadIdx.x; i < nb; i += gridDim.x * blockDim.x)
        b[i] = 0u;
}

__global__ void half_kernel(const float* __restrict__ in, __half* __restrict__ o, int n) {
    int i = blockIdx.x * blockDim.x + threadIdx.x;
    if (i < n) o[i] = __float2half(in[i]);
}

// ---------------- input MLP ----------------
__global__ void input_mlp_kernel(const float* __restrict__ x, const float* __restrict__ nrm,
                                 const float* __restrict__ w1, const float* __restrict__ b1,
                                 const float* __restrict__ w2, const float* __restrict__ b2,
                                 float* __restrict__ h, float* __restrict__ x2) {
    __shared__ float sw1[10 * 32], sb1[32], sw2[32 * 64], sb2[64], snrm[10];
    for (int idx = threadIdx.x; idx < 320; idx += blockDim.x) sw1[idx] = w1[idx];
    for (int idx = threadIdx.x; idx < 2048; idx += blockDim.x) sw2[idx] = w2[idx];
    if (threadIdx.x < 32) sb1[threadIdx.x] = b1[threadIdx.x];
    if (threadIdx.x < 64) sb2[threadIdx.x] = b2[threadIdx.x];
    if (threadIdx.x < 10) snrm[threadIdx.x] = nrm[threadIdx.x];
    __syncthreads();
    int n = blockIdx.x * blockDim.x + threadIdx.x;
    float xv[10];
#pragma unroll
    for (int c = 0; c < 10; c++) xv[c] = x[n * 10 + c] * snrm[c];
    float a[32];
#pragma unroll
    for (int o = 0; o < 32; o++) {
        float acc = sb1[o];
#pragma unroll
        for (int c = 0; c < 10; c++) acc = fmaf(xv[c], sw1[c * 32 + o], acc);
        a[o] = eluf(acc);
    }
    float ss = 0.f;
#pragma unroll 4
    for (int o = 0; o < 64; o++) {
        float acc = sb2[o];
#pragma unroll
        for (int c = 0; c < 32; c++) acc = fmaf(a[c], sw2[c * 64 + o], acc);
        acc = eluf(acc);
        h[(size_t)n * 64 + o] = acc;
        ss = fmaf(acc, acc, ss);
    }
    x2[n] = ss;
}

// ---------------- fp16 screen kNN: fused scan, per-candidate insertion, no self check ----------------
#define SM_Q 0
#define SM_C 9216
#define SM_X2M 27648
#define KNN_SMEM 28160
#define TS 144

template <int N>
__global__ void __launch_bounds__(128, 5) knn_screen_kernel(
    const __half* __restrict__ hq, const float* __restrict__ x2,
    float* __restrict__ part_d, int* __restrict__ part_i) {
    extern __shared__ unsigned char sm_raw[];
    const unsigned sb = (unsigned)__cvta_generic_to_shared(sm_raw);
    const int b = blockIdx.z, ch = blockIdx.y;
    const int i0 = blockIdx.x * 64;
    const int tid = threadIdx.x, lane = tid & 31, w = tid >> 5;
    const int j0 = ch * (N / CH), j1 = j0 + (N / CH);
    const __half* hb = hq + (size_t)b * N * 64;

    for (int idx = tid; idx < 64 * 8; idx += 128) {
        int r = idx >> 3, c = idx & 7;
        *(uint4*)(sm_raw + SM_Q + r * TS + c * 16) = *(const uint4*)(hb + (size_t)(i0 + r) * 64 + c * 8);
    }

    const int sub = lane >> 3, l7 = lane & 7;
    const int r0 = 16 * w + (lane >> 2);
    const int q0 = i0 + r0, q1 = q0 + 8;
    const float x2q0 = x2[b * N + q0];
    const float x2q1 = x2[b * N + q1];
    const int dcol = (lane & 3) * 2;

    float bd0[8], bd1[8]; int bi0[8], bi1[8];
#pragma unroll
    for (int r = 0; r < 8; r++) { bd0[r] = 3e38f; bi0[r] = 0; bd1[r] = 3e38f; bi1[r] = 0; }

    const int arow = 16 * w + l7 + ((sub & 1) ? 8 : 0);
    const unsigned aoff = (unsigned)(arow * TS + ((sub >> 1) ? 16 : 0));
    const unsigned boff = (unsigned)(l7 * TS + (((lane >> 3) & 1) ? 16 : 0));

    for (int jt = j0; jt < j1; jt += 128) {
        for (int idx = tid; idx < 128 * 8; idx += 128) {
            int r = idx >> 3, c = idx & 7;
            *(uint4*)(sm_raw + SM_C + r * TS + c * 16) = *(const uint4*)(hb + (size_t)(jt + r) * 64 + c * 8);
        }
        ((float*)(sm_raw + SM_X2M))[tid] = -0.5f * x2[b * N + jt + tid];
        __syncthreads();

#pragma unroll 1
        for (int half = 0; half < 2; half++) {
            const int ntb = half * 8;
            float acc[8][4];
#pragma unroll
            for (int nt = 0; nt < 8; nt++) {
                float2 v = *(const float2*)(sm_raw + SM_X2M + (8 * (ntb + nt) + dcol) * 4);
                acc[nt][0] = v.x; acc[nt][1] = v.y;
                acc[nt][2] = v.x; acc[nt][3] = v.y;
            }
#pragma unroll 1
            for (int ks = 0; ks < 4; ks++) {
                unsigned ah[4];
                ldm4(ah, sb + SM_Q + aoff + ks * 32);
                unsigned bah = sb + SM_C + boff + (unsigned)(ntb * 8 * TS) + ks * 32;
#pragma unroll
                for (int nt = 0; nt < 8; nt++) {
                    unsigned bh[2];
                    ldm2(bh, bah);
                    mma16816h(acc[nt], ah, bh);
                    bah += 8 * TS;
                }
            }
            // per-candidate insertion scan (no self check; rescore filters self)
#pragma unroll
            for (int nt = 0; nt < 8; nt++) {
#pragma unroll
                for (int e = 0; e < 2; e++) {
                    const int j = jt + 8 * (ntb + nt) + dcol + e;
                    float d0 = fmaf(-2.f, acc[nt][e], x2q0);
                    if (d0 < bd0[7]) {
                        bd0[7] = d0; bi0[7] = j;
#pragma unroll
                        for (int r = 7; r > 0; --r) {
                            if (bd0[r] < bd0[r - 1]) {
                                float tb = bd0[r]; bd0[r] = bd0[r - 1]; bd0[r - 1] = tb;
                                int ti = bi0[r]; bi0[r] = bi0[r - 1]; bi0[r - 1] = ti;
                            }
                        }
                    }
                    float d1 = fmaf(-2.f, acc[nt][e + 2], x2q1);
                    if (d1 < bd1[7]) {
                        bd1[7] = d1; bi1[7] = j;
#pragma unroll
                        for (int r = 7; r > 0; --r) {
                            if (bd1[r] < bd1[r - 1]) {
                                float tb = bd1[r]; bd1[r] = bd1[r - 1]; bd1[r - 1] = tb;
                                int ti = bi1[r]; bi1[r] = bi1[r - 1]; bi1[r - 1] = ti;
                            }
                        }
                    }
                }
            }
        }
        __syncthreads();
    }

    // stage 4 partial lists per query row, then 4-way lexicographic merge
    {
        float* stg = (float*)(sm_raw + SM_C);
        const int slot = lane & 3;
        float* dst0 = stg + (r0 * 4 + slot) * 16;
        float* dst1 = stg + ((r0 + 8) * 4 + slot) * 16;
#pragma unroll
        for (int r = 0; r < 8; r++) {
            dst0[r] = bd0[r]; ((int*)dst0)[8 + r] = bi0[r];
            dst1[r] = bd1[r]; ((int*)dst1)[8 + r] = bi1[r];
        }
    }
    __syncthreads();
    if (tid < 64) {
        const float* qs = (const float*)(sm_raw + SM_C) + tid * 64;
        size_t base = (((size_t)(b * N + i0 + tid)) * CH + ch) * 8;
        int p[4] = {0, 0, 0, 0};
#pragma unroll
        for (int r = 0; r < 8; r++) {
            float bdv = 3.1e38f; int biv = 0x7fffffff; int bl = 0;
#pragma unroll
            for (int l = 0; l < 4; l++) {
                float dv = qs[l * 16 + (p[l] & 7)];
                int iv = ((const int*)qs)[l * 16 + 8 + (p[l] & 7)];
                bool ok = (p[l] < 8) && ((dv < bdv) || (dv == bdv && iv < biv));
                if (ok) { bdv = dv; biv = iv; bl = l; }
            }
            p[bl]++;
            part_d[base + r] = bdv;
            part_i[base + r] = biv;
        }
    }
}

// ---------------- select: merge CH sorted 8-lists -> RC=16 candidates ----------------
__global__ void knn_sel_kernel(const float* __restrict__ part_d, const int* __restrict__ part_i,
                               int* __restrict__ cand, int NB) {
    int q = blockIdx.x * blockDim.x + threadIdx.x;
    if (q >= NB) return;
    size_t base = (size_t)q * CH * 8;
    int p[CH];
#pragma unroll
    for (int l = 0; l < CH; l++) p[l] = 0;
#pragma unroll
    for (int r = 0; r < RC; r++) {
        float bdv = 3.1e38f; int biv = 0x7fffffff; int bl = 0;
#pragma unroll
        for (int l = 0; l < CH; l++) {
            float dv = part_d[base + l * 8 + (p[l] & 7)];
            int iv = part_i[base + l * 8 + (p[l] & 7)];
            bool ok = (p[l] < 8) && ((dv < bdv) || (dv == bdv && iv < biv));
            if (ok) { bdv = dv; biv = iv; bl = l; }
        }
        p[bl]++;
        cand[(size_t)q * RC + r] = biv;
    }
}

// ---------------- rescore: exact fp32 distance, self filtered -> top-8 ----------------
__global__ void __launch_bounds__(128) knn_rescore_kernel(
    const float* __restrict__ h, const float* __restrict__ x2,
    const int* __restrict__ cand, int* __restrict__ nbr, int N) {
    __shared__ float sd[8][RC];
    __shared__ int si[8][RC];
    const int qg = blockIdx.x * 8 + (threadIdx.x >> 4);
    const int t = threadIdx.x & 15;
    const int qq = threadIdx.x >> 4;
    const int b = qg / N;
    const float* hb = h + (size_t)b * N * 64;
    const int iq = qg - b * N;
    int j = cand[(size_t)qg * RC + t];
    const float* hi = hb + (size_t)iq * 64;
    const float* hj = hb + (size_t)j * 64;
    float a0 = 0.f, a1 = 0.f, a2 = 0.f, a3 = 0.f;
#pragma unroll
    for (int c = 0; c < 64; c += 4) {
        a0 = fmaf(hi[c + 0], hj[c + 0], a0);
        a1 = fmaf(hi[c + 1], hj[c + 1], a1);
        a2 = fmaf(hi[c + 2], hj[c + 2], a2);
        a3 = fmaf(hi[c + 3], hj[c + 3], a3);
    }
    float d = x2[qg] + x2[b * N + j] - 2.f * ((a0 + a1) + (a2 + a3));
    if (j == iq) d = 3.2e38f;   // self excluded here
    sd[qq][t] = d;
    si[qq][t] = j;
    __syncwarp();
    if (t == 0) {
        float bd[8]; int bi[8];
#pragma unroll
        for (int r = 0; r < 8; r++) { bd[r] = 3e38f; bi[r] = 0x7fffffff; }
#pragma unroll
        for (int c = 0; c < RC; c++) {
            float dv = sd[qq][c]; int iv = si[qq][c];
            bool ins = (dv < bd[7]) || (dv == bd[7] && iv < bi[7]);
            if (ins) {
                bd[7] = dv; bi[7] = iv;
#pragma unroll
                for (int r = 7; r > 0; --r) {
                    if (bd[r] < bd[r - 1] || (bd[r] == bd[r - 1] && bi[r] < bi[r - 1])) {
                        float tb = bd[r]; bd[r] = bd[r - 1]; bd[r - 1] = tb;
                        int ti = bi[r]; bi[r] = bi[r - 1]; bi[r - 1] = ti;
                    }
                }
            }
        }
#pragma unroll
        for (int r = 0; r < 8; r++) nbr[(size_t)qg * 8 + r] = bi[r];
    }
}

// ---------------- per-node projections for EdgeConv decomposition ----------------
__global__ void proj_kernel(const float* __restrict__ h, const float* __restrict__ wa,
                            float* __restrict__ Pd, float* __restrict__ Ps, int NB) {
    __shared__ float Wd[64 * 96];
    __shared__ float Ws[64 * 96];
    for (int idx = threadIdx.x; idx < 64 * 96; idx += blockDim.x) {
        float top = wa[idx];
        float bot = wa[64 * 96 + idx];
        Wd[idx] = top - bot;
        Ws[idx] = bot;
    }
    __syncthreads();
    int warp = (blockIdx.x * blockDim.x + threadIdx.x) >> 5;
    int lane = threadIdx.x & 31;
    int nwarps = (gridDim.x * blockDim.x) >> 5;
    for (int n = warp; n < NB; n += nwarps) {
        float h0 = h[(size_t)n * 64 + lane];
        float h1 = h[(size_t)n * 64 + 32 + lane];
        float d0 = 0, d1 = 0, d2 = 0, s0 = 0, s1 = 0, s2 = 0;
#pragma unroll
        for (int c = 0; c < 64; c++) {
            float hc = __shfl_sync(0xffffffffu, (c < 32) ? h0 : h1, c & 31);
            const float* wd = &Wd[c * 96 + lane];
            const float* ws = &Ws[c * 96 + lane];
            d0 = fmaf(hc, wd[0], d0);  d1 = fmaf(hc, wd[32], d1);  d2 = fmaf(hc, wd[64], d2);
            s0 = fmaf(hc, ws[0], s0);  s1 = fmaf(hc, ws[32], s1);  s2 = fmaf(hc, ws[64], s2);
        }
        Pd[(size_t)n * 96 + lane] = d0; Pd[(size_t)n * 96 + lane + 32] = d1; Pd[(size_t)n * 96 + lane + 64] = d2;
        Ps[(size_t)n * 96 + lane] = s0; Ps[(size_t)n * 96 + lane + 32] = s1; Ps[(size_t)n * 96 + lane + 64] = s2;
    }
}

// ---------------- EdgeConv: register-blocked ----------------
#define EC_SMEM (96*32*8 + 8*2*96*8*4)
__global__ void __launch_bounds__(256, 2) edgeconv_kernel(
    const float* __restrict__ Pd, const float* __restrict__ Ps,
    const float* __restrict__ b1, const float* __restrict__ w2,
    const float* __restrict__ b2, const int* __restrict__ nbr,
    unsigned* __restrict__ agg, int Nn) {
    extern __shared__ unsigned char ec_sm[];
    float2* sW2 = (float2*)ec_sm;
    float*  sHidBase = (float*)(ec_sm + 96 * 32 * 8);

    for (int idx = threadIdx.x; idx < 96 * 32; idx += 256)
        sW2[idx] = ((const float2*)w2)[idx];

    const int w = threadIdx.x >> 5, lane = threadIdx.x & 31;
    const int gn = blockIdx.x * 8 + w;
    const int b = gn / Nn;
    float* sF = sHidBase + (size_t)w * 2 * 96 * 8;
    float* sR = sF + 96 * 8;

    const float* pdi_p = Pd + (size_t)gn * 96;
    const float* psi_p = Ps + (size_t)gn * 96;
    float pdi0 = pdi_p[lane], pdi1 = pdi_p[lane + 32], pdi2 = pdi_p[lane + 64];
    float psi0 = psi_p[lane], psi1 = psi_p[lane + 32], psi2 = psi_p[lane + 64];
    float b10 = b1[lane], b11 = b1[lane + 32], b12 = b1[lane + 64];

    int jn[8];
#pragma unroll
    for (int k = 0; k < 8; k++) jn[k] = nbr[(size_t)gn * 8 + k];

#pragma unroll 1
    for (int k = 0; k < 8; k++) {
        size_t jg = (size_t)b * Nn + jn[k];
        const float* pdj = Pd + jg * 96;
        const float* psj = Ps + jg * 96;
        float pj0 = pdj[lane], pj1 = pdj[lane + 32], pj2 = pdj[lane + 64];
        float sj0 = psj[lane], sj1 = psj[lane + 32], sj2 = psj[lane + 64];
        sF[lane * 8 + k]        = eluf(pdi0 + sj0 + b10);
        sF[(lane + 32) * 8 + k] = eluf(pdi1 + sj1 + b11);
        sF[(lane + 64) * 8 + k] = eluf(pdi2 + sj2 + b12);
        sR[lane * 8 + k]        = eluf(pj0 + psi0 + b10);
        sR[(lane + 32) * 8 + k] = eluf(pj1 + psi1 + b11);
        sR[(lane + 64) * 8 + k] = eluf(pj2 + psi2 + b12);
    }
    __syncthreads();

    float aF[8][2], aR[8][2];
#pragma unroll
    for (int e = 0; e < 8; e++) { aF[e][0] = aF[e][1] = aR[e][0] = aR[e][1] = 0.f; }

#pragma unroll 4
    for (int hh = 0; hh < 96; hh++) {
        float2 wv = sW2[hh * 32 + lane];
        float4 f03 = *(const float4*)&sF[hh * 8];
        float4 f47 = *(const float4*)&sF[hh * 8 + 4];
        float4 r03 = *(const float4*)&sR[hh * 8];
        float4 r47 = *(const float4*)&sR[hh * 8 + 4];
        aF[0][0] = fmaf(f03.x, wv.x, aF[0][0]); aF[0][1] = fmaf(f03.x, wv.y, aF[0][1]);
        aF[1][0] = fmaf(f03.y, wv.x, aF[1][0]); aF[1][1] = fmaf(f03.y, wv.y, aF[1][1]);
        aF[2][0] = fmaf(f03.z, wv.x, aF[2][0]); aF[2][1] = fmaf(f03.z, wv.y, aF[2][1]);
        aF[3][0] = fmaf(f03.w, wv.x, aF[3][0]); aF[3][1] = fmaf(f03.w, wv.y, aF[3][1]);
        aF[4][0] = fmaf(f47.x, wv.x, aF[4][0]); aF[4][1] = fmaf(f47.x, wv.y, aF[4][1]);
        aF[5][0] = fmaf(f47.y, wv.x, aF[5][0]); aF[5][1] = fmaf(f47.y, wv.y, aF[5][1]);
        aF[6][0] = fmaf(f47.z, wv.x, aF[6][0]); aF[6][1] = fmaf(f47.z, wv.y, aF[6][1]);
        aF[7][0] = fmaf(f47.w, wv.x, aF[7][0]); aF[7][1] = fmaf(f47.w, wv.y, aF[7][1]);
        aR[0][0] = fmaf(r03.x, wv.x, aR[0][0]); aR[0][1] = fmaf(r03.x, wv.y, aR[0][1]);
        aR[1][0] = fmaf(r03.y, wv.x, aR[1][0]); aR[1][1] = fmaf(r03.y, wv.y, aR[1][1]);
        aR[2][0] = fmaf(r03.z, wv.x, aR[2][0]); aR[2][1] = fmaf(r03.z, wv.y, aR[2][1]);
        aR[3][0] = fmaf(r03.w, wv.x, aR[3][0]); aR[3][1] = fmaf(r03.w, wv.y, aR[3][1]);
        aR[4][0] = fmaf(r47.x, wv.x, aR[4][0]); aR[4][1] = fmaf(r47.x, wv.y, aR[4][1]);
        aR[5][0] = fmaf(r47.y, wv.x, aR[5][0]); aR[5][1] = fmaf(r47.y, wv.y, aR[5][1]);
        aR[6][0] = fmaf(r47.z, wv.x, aR[6][0]); aR[6][1] = fmaf(r47.z, wv.y, aR[6][1]);
        aR[7][0] = fmaf(r47.w, wv.x, aR[7][0]); aR[7][1] = fmaf(r47.w, wv.y, aR[7][1]);
    }

    const float bo0 = b2[2 * lane], bo1 = b2[2 * lane + 1];
    unsigned fm0 = 0u, fm1 = 0u;
#pragma unroll
    for (int e = 0; e < 8; e++) {
        fm0 = max(fm0, encf(eluf(aF[e][0] + bo0)));
        fm1 = max(fm1, encf(eluf(aF[e][1] + bo1)));
    }
    atomicMax(agg + (size_t)gn * 64 + 2 * lane,     fm0);
    atomicMax(agg + (size_t)gn * 64 + 2 * lane + 1, fm1);
#pragma unroll
    for (int e = 0; e < 8; e++) {
        size_t jg = (size_t)b * Nn + jn[e];
        atomicMax(agg + jg * 64 + 2 * lane,     encf(eluf(aR[e][0] + bo0)));
        atomicMax(agg + jg * 64 + 2 * lane + 1, encf(eluf(aR[e][1] + bo1)));
    }
}

// ---------------- decode + pairwise max pool + sq-norm ----------------
__global__ void pool_kernel(const unsigned* __restrict__ agg, float* __restrict__ h3,
                            float* __restrict__ x2b) {
    int w = (blockIdx.x * blockDim.x + threadIdx.x) >> 5;
    int lane = threadIdx.x & 31;
    int b = w / N2c;
    int i = w - b * N2c;
    size_t s0 = ((size_t)(b * N1c + 2 * i)) * 64;
    float ss = 0.f;
#pragma unroll
    for (int r = 0; r < 2; r++) {
        int c = lane + 32 * r;
        float v = fmaxf(decf(agg[s0 + c]), decf(agg[s0 + 64 + c]));
        h3[(size_t)w * 64 + c] = v;
        ss = fmaf(v, v, ss);
    }
    for (int o = 16; o > 0; o >>= 1) ss += __shfl_down_sync(0xffffffffu, ss, o);
    if (lane == 0) x2b[w] = ss;
}

// ---------------- global max pool + head MLP ----------------
__global__ void final_kernel(const unsigned* __restrict__ agg,
                             const float* __restrict__ w1, const float* __restrict__ bb1,
                             const float* __restrict__ w2, const float* __restrict__ bb2,
                             const float* __restrict__ w3, const float* __restrict__ bb3,
                             float* __restrict__ out) {
    __shared__ float red[256];
    __shared__ float gv[64], t1[64], t2[32];
    int b = blockIdx.x;
    int c = threadIdx.x & 63, grp = threadIdx.x >> 6;
    float m = -3e38f;
    for (int n = grp; n < N2c; n += 4)
        m = fmaxf(m, decf(agg[((size_t)(b * N2c + n)) * 64 + c]));
    red[threadIdx.x] = m;
    __syncthreads();
    if (threadIdx.x < 64) {
        m = fmaxf(fmaxf(red[threadIdx.x], red[threadIdx.x + 64]),
                  fmaxf(red[threadIdx.x + 128], red[threadIdx.x + 192]));
        gv[threadIdx.x] = m;
    }
    __syncthreads();
    if (threadIdx.x < 64) {
        float acc = bb1[threadIdx.x];
#pragma unroll
        for (int cc = 0; cc < 64; cc++) acc = fmaf(gv[cc], w1[cc * 64 + threadIdx.x], acc);
        t1[threadIdx.x] = eluf(acc);
    }
    __syncthreads();
    if (threadIdx.x < 32) {
        float acc = bb2[threadIdx.x];
#pragma unroll
        for (int cc = 0; cc < 64; cc++) acc = fmaf(t1[cc], w2[cc * 32 + threadIdx.x], acc);
        t2[threadIdx.x] = eluf(acc);
    }
    __syncthreads();
    if (threadIdx.x == 0) {
        float o0 = bb3[0], o1 = bb3[1];
#pragma unroll
        for (int cc = 0; cc < 32; cc++) {
            o0 = fmaf(t2[cc], w3[cc * 2 + 0], o0);
            o1 = fmaf(t2[cc], w3[cc * 2 + 1], o1);
        }
        float met = fmaxf(o0, 0.f) + log1pf(expf(-fabsf(o0)));
        float sig = 1.f / (1.f + expf(-o1));
        float phi = 3.14159265358979323846f * (2.f * sig - 1.f);
        out[b * 2 + 0] = met;
        out[b * 2 + 1] = phi;
    }
}

// ---------------- launch ----------------
extern "C" void kernel_launch(void* const* d_in, const int* in_sizes, int n_in,
                              void* d_out, int out_size) {
    const float* x      = (const float*)d_in[0];
    const float* nrm    = (const float*)d_in[1];
    const float* w_in1  = (const float*)d_in[2];
    const float* b_in1  = (const float*)d_in[3];
    const float* w_in2  = (const float*)d_in[4];
    const float* b_in2  = (const float*)d_in[5];
    const float* w_c1a  = (const float*)d_in[6];
    const float* b_c1a  = (const float*)d_in[7];
    const float* w_c1b  = (const float*)d_in[8];
    const float* b_c1b  = (const float*)d_in[9];
    const float* w_c2a  = (const float*)d_in[10];
    const float* b_c2a  = (const float*)d_in[11];
    const float* w_c2b  = (const float*)d_in[12];
    const float* b_c2b  = (const float*)d_in[13];
    const float* w_o1   = (const float*)d_in[14];
    const float* b_o1   = (const float*)d_in[15];
    const float* w_o2   = (const float*)d_in[16];
    const float* b_o2   = (const float*)d_in[17];
    const float* w_o3   = (const float*)d_in[18];
    const float* b_o3   = (const float*)d_in[19];
    float* out = (float*)d_out;

    float *h1, *x2a, *Pd1, *Ps1, *h3, *x2b, *Pd2, *Ps2, *pd1, *pd2;
    int *nbr1, *nbr2, *pi1, *pi2, *cand1, *cand2;
    unsigned *agg1, *agg2;
    __half *hq1, *hq2;
    cudaGetSymbolAddress((void**)&h1,   g_h1);
    cudaGetSymbolAddress((void**)&x2a,  g_x2a);
    cudaGetSymbolAddress((void**)&nbr1, g_nbr1);
    cudaGetSymbolAddress((void**)&Pd1,  g_Pd1);
    cudaGetSymbolAddress((void**)&Ps1,  g_Ps1);
    cudaGetSymbolAddress((void**)&agg1, g_agg1);
    cudaGetSymbolAddress((void**)&h3,   g_h3);
    cudaGetSymbolAddress((void**)&x2b,  g_x2b);
    cudaGetSymbolAddress((void**)&nbr2, g_nbr2);
    cudaGetSymbolAddress((void**)&Pd2,  g_Pd2);
    cudaGetSymbolAddress((void**)&Ps2,  g_Ps2);
    cudaGetSymbolAddress((void**)&agg2, g_agg2);
    cudaGetSymbolAddress((void**)&pd1,  g_pd1);
    cudaGetSymbolAddress((void**)&pi1,  g_pi1);
    cudaGetSymbolAddress((void**)&pd2,  g_pd2);
    cudaGetSymbolAddress((void**)&pi2,  g_pi2);
    cudaGetSymbolAddress((void**)&cand1, g_cand1);
    cudaGetSymbolAddress((void**)&cand2, g_cand2);
    cudaGetSymbolAddress((void**)&hq1,  g_hq1);
    cudaGetSymbolAddress((void**)&hq2,  g_hq2);

    cudaFuncSetAttribute(knn_screen_kernel<N1c>, cudaFuncAttributeMaxDynamicSharedMemorySize, KNN_SMEM);
    cudaFuncSetAttribute(knn_screen_kernel<N2c>, cudaFuncAttributeMaxDynamicSharedMemorySize, KNN_SMEM);
    cudaFuncSetAttribute(edgeconv_kernel, cudaFuncAttributeMaxDynamicSharedMemorySize, EC_SMEM);

    // index 0
    zero2_kernel<<<1024, 256>>>(agg1, Bc * N1c * Hc, agg2, Bc * N2c * Hc);
    // index 1
    input_mlp_kernel<<<(Bc * N1c) / 128, 128>>>(x, nrm, w_in1, b_in1, w_in2, b_in2, h1, x2a);
    // index 2
    half_kernel<<<(Bc * N1c * Hc + 255) / 256, 256>>>(h1, hq1, Bc * N1c * Hc);
    // index 3 <-- ncu capture slot
    knn_screen_kernel<N1c><<<dim3(N1c / 64, CH, Bc), 128, KNN_SMEM>>>(hq1, x2a, pd1, pi1);
    knn_sel_kernel<<<(Bc * N1c + 255) / 256, 256>>>(pd1, pi1, cand1, Bc * N1c);
    knn_rescore_kernel<<<(Bc * N1c) / 8, 128>>>(h1, x2a, cand1, nbr1, N1c);
    proj_kernel<<<(Bc * N1c) / 8, 256>>>(h1, w_c1a, Pd1, Ps1, Bc * N1c);
    edgeconv_kernel<<<(Bc * N1c) / 8, 256, EC_SMEM>>>(Pd1, Ps1, b_c1a, w_c1b, b_c1b, nbr1, agg1, N1c);

    pool_kernel<<<(Bc * N2c) / 8, 256>>>(agg1, h3, x2b);
    half_kernel<<<(Bc * N2c * Hc + 255) / 256, 256>>>(h3, hq2, Bc * N2c * Hc);

    knn_screen_kernel<N2c><<<dim3(N2c / 64, CH, Bc), 128, KNN_SMEM>>>(hq2, x2b, pd2, pi2);
    knn_sel_kernel<<<(Bc * N2c + 255) / 256, 256>>>(pd2, pi2, cand2, Bc * N2c);
    knn_rescore_kernel<<<(Bc * N2c) / 8, 128>>>(h3, x2b, cand2, nbr2, N2c);
    proj_kernel<<<(Bc * N2c) / 8, 256>>>(h3, w_c2a, Pd2, Ps2, Bc * N2c);
    edgeconv_kernel<<<(Bc * N2c) / 8, 256, EC_SMEM>>>(Pd2, Ps2, b_c2a, w_c2b, b_c2b, nbr2, agg2, N2c);

    final_kernel<<<Bc, 256>>>(agg2, w_o1, b_o1, w_o2, b_o2, w_o3, b_o3, out);
}

// round 16
// speedup vs baseline: 1.0925x; 1.0498x over previous
#include <cuda_runtime.h>
#include <cuda_bf16.h>
#include <cuda_fp16.h>
#include <math.h>
#include <cstdint>

#define Bc 8
#define N1c 4096
#define N2c 2048
#define Hc 64
#define Kc 8
#define CH 8    // candidate chunks per kNN pass
#define RC 16   // rescored candidates per query

// ---------------- device scratch (no cudaMalloc allowed) ----------------
__device__ float    g_h1 [Bc*N1c*Hc];
__device__ float    g_x2a[Bc*N1c];
__device__ int      g_nbr1[Bc*N1c*Kc];
__device__ float    g_Pd1[Bc*N1c*96];
__device__ float    g_Ps1[Bc*N1c*96];
__device__ unsigned g_agg1[Bc*N1c*Hc];
__device__ float    g_h3 [Bc*N2c*Hc];
__device__ float    g_x2b[Bc*N2c];
__device__ int      g_nbr2[Bc*N2c*Kc];
__device__ float    g_Pd2[Bc*N2c*96];
__device__ float    g_Ps2[Bc*N2c*96];
__device__ unsigned g_agg2[Bc*N2c*Hc];
__device__ float    g_pd1[Bc*N1c*CH*Kc];
__device__ int      g_pi1[Bc*N1c*CH*Kc];
__device__ float    g_pd2[Bc*N2c*CH*Kc];
__device__ int      g_pi2[Bc*N2c*CH*Kc];
__device__ int      g_cand1[Bc*N1c*RC];
__device__ int      g_cand2[Bc*N2c*RC];
__device__ __half   g_hq1[Bc*N1c*Hc];
__device__ __half   g_hq2[Bc*N2c*Hc];

// ---------------- helpers ----------------
__device__ __forceinline__ float eluf(float x) { return x > 0.f ? x : expm1f(x); }

__device__ __forceinline__ unsigned encf(float f) {
    unsigned u = __float_as_uint(f);
    return (u & 0x80000000u) ? ~u : (u | 0x80000000u);
}
__device__ __forceinline__ float decf(unsigned u) {
    return __uint_as_float((u & 0x80000000u) ? (u ^ 0x80000000u) : ~u);
}

__device__ __forceinline__ void ldm4(unsigned* r, unsigned addr) {
    asm volatile("ldmatrix.sync.aligned.m8n8.x4.shared.b16 {%0,%1,%2,%3},[%4];"
                 : "=r"(r[0]), "=r"(r[1]), "=r"(r[2]), "=r"(r[3]) : "r"(addr));
}
__device__ __forceinline__ void ldm2(unsigned* r, unsigned addr) {
    asm volatile("ldmatrix.sync.aligned.m8n8.x2.shared.b16 {%0,%1},[%2];"
                 : "=r"(r[0]), "=r"(r[1]) : "r"(addr));
}
__device__ __forceinline__ void mma16816h(float* c, const unsigned* a, const unsigned* b) {
    asm volatile("mma.sync.aligned.m16n8k16.row.col.f32.f16.f16.f32 "
                 "{%0,%1,%2,%3},{%4,%5,%6,%7},{%8,%9},{%0,%1,%2,%3};"
                 : "+f"(c[0]), "+f"(c[1]), "+f"(c[2]), "+f"(c[3])
                 : "r"(a[0]), "r"(a[1]), "r"(a[2]), "r"(a[3]), "r"(b[0]), "r"(b[1]));
}

// ---------------- zero both agg arrays in ONE launch ----------------
__global__ void zero2_kernel(unsigned* a, int na, unsigned* b, int nb) {
    for (int i = blockIdx.x * blockDim.x + threadIdx.x; i < na; i += gridDim.x * blockDim.x)
        a[i] = 0u;
    for (int i = blockIdx.x * blockDim.x + threadIdx.x; i < nb; i += gridDim.x * blockDim.x)
        b[i] = 0u;
}

__global__ void half_kernel(const float* __restrict__ in, __half* __restrict__ o, int n) {
    int i = blockIdx.x * blockDim.x + threadIdx.x;
    if (i < n) o[i] = __float2half(in[i]);
}

// ---------------- input MLP ----------------
__global__ void input_mlp_kernel(const float* __restrict__ x, const float* __restrict__ nrm,
                                 const float* __restrict__ w1, const float* __restrict__ b1,
                                 const float* __restrict__ w2, const float* __restrict__ b2,
                                 float* __restrict__ h, float* __restrict__ x2) {
    __shared__ float sw1[10 * 32], sb1[32], sw2[32 * 64], sb2[64], snrm[10];
    for (int idx = threadIdx.x; idx < 320; idx += blockDim.x) sw1[idx] = w1[idx];
    for (int idx = threadIdx.x; idx < 2048; idx += blockDim.x) sw2[idx] = w2[idx];
    if (threadIdx.x < 32) sb1[threadIdx.x] = b1[threadIdx.x];
    if (threadIdx.x < 64) sb2[threadIdx.x] = b2[threadIdx.x];
    if (threadIdx.x < 10) snrm[threadIdx.x] = nrm[threadIdx.x];
    __syncthreads();
    int n = blockIdx.x * blockDim.x + threadIdx.x;
    float xv[10];
#pragma unroll
    for (int c = 0; c < 10; c++) xv[c] = x[n * 10 + c] * snrm[c];
    float a[32];
#pragma unroll
    for (int o = 0; o < 32; o++) {
        float acc = sb1[o];
#pragma unroll
        for (int c = 0; c < 10; c++) acc = fmaf(xv[c], sw1[c * 32 + o], acc);
        a[o] = eluf(acc);
    }
    float ss = 0.f;
#pragma unroll 4
    for (int o = 0; o < 64; o++) {
        float acc = sb2[o];
#pragma unroll
        for (int c = 0; c < 32; c++) acc = fmaf(a[c], sw2[c * 64 + o], acc);
        acc = eluf(acc);
        h[(size_t)n * 64 + o] = acc;
        ss = fmaf(acc, acc, ss);
    }
    x2[n] = ss;
}

// ---------------- fp16 screen kNN (R15 structure, unchanged) ----------------
#define SM_Q 0
#define SM_C 9216
#define SM_X2M 27648
#define KNN_SMEM 28160
#define TS 144

template <int N>
__global__ void __launch_bounds__(128, 5) knn_screen_kernel(
    const __half* __restrict__ hq, const float* __restrict__ x2,
    float* __restrict__ part_d, int* __restrict__ part_i) {
    extern __shared__ unsigned char sm_raw[];
    const unsigned sb = (unsigned)__cvta_generic_to_shared(sm_raw);
    const int b = blockIdx.z, ch = blockIdx.y;
    const int i0 = blockIdx.x * 64;
    const int tid = threadIdx.x, lane = tid & 31, w = tid >> 5;
    const int j0 = ch * (N / CH), j1 = j0 + (N / CH);
    const __half* hb = hq + (size_t)b * N * 64;

    for (int idx = tid; idx < 64 * 8; idx += 128) {
        int r = idx >> 3, c = idx & 7;
        *(uint4*)(sm_raw + SM_Q + r * TS + c * 16) = *(const uint4*)(hb + (size_t)(i0 + r) * 64 + c * 8);
    }

    const int sub = lane >> 3, l7 = lane & 7;
    const int r0 = 16 * w + (lane >> 2);
    const int q0 = i0 + r0, q1 = q0 + 8;
    const float x2q0 = x2[b * N + q0];
    const float x2q1 = x2[b * N + q1];
    const int dcol = (lane & 3) * 2;

    float bd0[8], bd1[8]; int bi0[8], bi1[8];
#pragma unroll
    for (int r = 0; r < 8; r++) { bd0[r] = 3e38f; bi0[r] = 0; bd1[r] = 3e38f; bi1[r] = 0; }

    const int arow = 16 * w + l7 + ((sub & 1) ? 8 : 0);
    const unsigned aoff = (unsigned)(arow * TS + ((sub >> 1) ? 16 : 0));
    const unsigned boff = (unsigned)(l7 * TS + (((lane >> 3) & 1) ? 16 : 0));

    for (int jt = j0; jt < j1; jt += 128) {
        for (int idx = tid; idx < 128 * 8; idx += 128) {
            int r = idx >> 3, c = idx & 7;
            *(uint4*)(sm_raw + SM_C + r * TS + c * 16) = *(const uint4*)(hb + (size_t)(jt + r) * 64 + c * 8);
        }
        ((float*)(sm_raw + SM_X2M))[tid] = -0.5f * x2[b * N + jt + tid];
        __syncthreads();

#pragma unroll 1
        for (int half = 0; half < 2; half++) {
            const int ntb = half * 8;
            float acc[8][4];
#pragma unroll
            for (int nt = 0; nt < 8; nt++) {
                float2 v = *(const float2*)(sm_raw + SM_X2M + (8 * (ntb + nt) + dcol) * 4);
                acc[nt][0] = v.x; acc[nt][1] = v.y;
                acc[nt][2] = v.x; acc[nt][3] = v.y;
            }
#pragma unroll 1
            for (int ks = 0; ks < 4; ks++) {
                unsigned ah[4];
                ldm4(ah, sb + SM_Q + aoff + ks * 32);
                unsigned bah = sb + SM_C + boff + (unsigned)(ntb * 8 * TS) + ks * 32;
#pragma unroll
                for (int nt = 0; nt < 8; nt++) {
                    unsigned bh[2];
                    ldm2(bh, bah);
                    mma16816h(acc[nt], ah, bh);
                    bah += 8 * TS;
                }
            }
#pragma unroll
            for (int nt = 0; nt < 8; nt++) {
#pragma unroll
                for (int e = 0; e < 2; e++) {
                    const int j = jt + 8 * (ntb + nt) + dcol + e;
                    float d0 = fmaf(-2.f, acc[nt][e], x2q0);
                    if (d0 < bd0[7]) {
                        bd0[7] = d0; bi0[7] = j;
#pragma unroll
                        for (int r = 7; r > 0; --r) {
                            if (bd0[r] < bd0[r - 1]) {
                                float tb = bd0[r]; bd0[r] = bd0[r - 1]; bd0[r - 1] = tb;
                                int ti = bi0[r]; bi0[r] = bi0[r - 1]; bi0[r - 1] = ti;
                            }
                        }
                    }
                    float d1 = fmaf(-2.f, acc[nt][e + 2], x2q1);
                    if (d1 < bd1[7]) {
                        bd1[7] = d1; bi1[7] = j;
#pragma unroll
                        for (int r = 7; r > 0; --r) {
                            if (bd1[r] < bd1[r - 1]) {
                                float tb = bd1[r]; bd1[r] = bd1[r - 1]; bd1[r - 1] = tb;
                                int ti = bi1[r]; bi1[r] = bi1[r - 1]; bi1[r - 1] = ti;
                            }
                        }
                    }
                }
            }
        }
        __syncthreads();
    }

    {
        float* stg = (float*)(sm_raw + SM_C);
        const int slot = lane & 3;
        float* dst0 = stg + (r0 * 4 + slot) * 16;
        float* dst1 = stg + ((r0 + 8) * 4 + slot) * 16;
#pragma unroll
        for (int r = 0; r < 8; r++) {
            dst0[r] = bd0[r]; ((int*)dst0)[8 + r] = bi0[r];
            dst1[r] = bd1[r]; ((int*)dst1)[8 + r] = bi1[r];
        }
    }
    __syncthreads();
    if (tid < 64) {
        const float* qs = (const float*)(sm_raw + SM_C) + tid * 64;
        size_t base = (((size_t)(b * N + i0 + tid)) * CH + ch) * 8;
        int p[4] = {0, 0, 0, 0};
#pragma unroll
        for (int r = 0; r < 8; r++) {
            float bdv = 3.1e38f; int biv = 0x7fffffff; int bl = 0;
#pragma unroll
            for (int l = 0; l < 4; l++) {
                float dv = qs[l * 16 + (p[l] & 7)];
                int iv = ((const int*)qs)[l * 16 + 8 + (p[l] & 7)];
                bool ok = (p[l] < 8) && ((dv < bdv) || (dv == bdv && iv < biv));
                if (ok) { bdv = dv; biv = iv; bl = l; }
            }
            p[bl]++;
            part_d[base + r] = bdv;
            part_i[base + r] = biv;
        }
    }
}

// ---------------- select: merge CH sorted 8-lists -> RC=16 candidates ----------------
__global__ void knn_sel_kernel(const float* __restrict__ part_d, const int* __restrict__ part_i,
                               int* __restrict__ cand, int NB) {
    int q = blockIdx.x * blockDim.x + threadIdx.x;
    if (q >= NB) return;
    size_t base = (size_t)q * CH * 8;
    int p[CH];
#pragma unroll
    for (int l = 0; l < CH; l++) p[l] = 0;
#pragma unroll
    for (int r = 0; r < RC; r++) {
        float bdv = 3.1e38f; int biv = 0x7fffffff; int bl = 0;
#pragma unroll
        for (int l = 0; l < CH; l++) {
            float dv = part_d[base + l * 8 + (p[l] & 7)];
            int iv = part_i[base + l * 8 + (p[l] & 7)];
            bool ok = (p[l] < 8) && ((dv < bdv) || (dv == bdv && iv < biv));
            if (ok) { bdv = dv; biv = iv; bl = l; }
        }
        p[bl]++;
        cand[(size_t)q * RC + r] = biv;
    }
}

// ---------------- rescore: exact fp32 distance, self filtered -> top-8 ----------------
__global__ void __launch_bounds__(128) knn_rescore_kernel(
    const float* __restrict__ h, const float* __restrict__ x2,
    const int* __restrict__ cand, int* __restrict__ nbr, int N) {
    __shared__ float sd[8][RC];
    __shared__ int si[8][RC];
    const int qg = blockIdx.x * 8 + (threadIdx.x >> 4);
    const int t = threadIdx.x & 15;
    const int qq = threadIdx.x >> 4;
    const int b = qg / N;
    const float* hb = h + (size_t)b * N * 64;
    const int iq = qg - b * N;
    int j = cand[(size_t)qg * RC + t];
    const float* hi = hb + (size_t)iq * 64;
    const float* hj = hb + (size_t)j * 64;
    float a0 = 0.f, a1 = 0.f, a2 = 0.f, a3 = 0.f;
#pragma unroll
    for (int c = 0; c < 64; c += 4) {
        a0 = fmaf(hi[c + 0], hj[c + 0], a0);
        a1 = fmaf(hi[c + 1], hj[c + 1], a1);
        a2 = fmaf(hi[c + 2], hj[c + 2], a2);
        a3 = fmaf(hi[c + 3], hj[c + 3], a3);
    }
    float d = x2[qg] + x2[b * N + j] - 2.f * ((a0 + a1) + (a2 + a3));
    if (j == iq) d = 3.2e38f;
    sd[qq][t] = d;
    si[qq][t] = j;
    __syncwarp();
    if (t == 0) {
        float bd[8]; int bi[8];
#pragma unroll
        for (int r = 0; r < 8; r++) { bd[r] = 3e38f; bi[r] = 0x7fffffff; }
#pragma unroll
        for (int c = 0; c < RC; c++) {
            float dv = sd[qq][c]; int iv = si[qq][c];
            bool ins = (dv < bd[7]) || (dv == bd[7] && iv < bi[7]);
            if (ins) {
                bd[7] = dv; bi[7] = iv;
#pragma unroll
                for (int r = 7; r > 0; --r) {
                    if (bd[r] < bd[r - 1] || (bd[r] == bd[r - 1] && bi[r] < bi[r - 1])) {
                        float tb = bd[r]; bd[r] = bd[r - 1]; bd[r - 1] = tb;
                        int ti = bi[r]; bi[r] = bi[r - 1]; bi[r - 1] = ti;
                    }
                }
            }
        }
#pragma unroll
        for (int r = 0; r < 8; r++) nbr[(size_t)qg * 8 + r] = bi[r];
    }
}

// ---------------- per-node projections for EdgeConv decomposition ----------------
__global__ void proj_kernel(const float* __restrict__ h, const float* __restrict__ wa,
                            float* __restrict__ Pd, float* __restrict__ Ps, int NB) {
    __shared__ float Wd[64 * 96];
    __shared__ float Ws[64 * 96];
    for (int idx = threadIdx.x; idx < 64 * 96; idx += blockDim.x) {
        float top = wa[idx];
        float bot = wa[64 * 96 + idx];
        Wd[idx] = top - bot;
        Ws[idx] = bot;
    }
    __syncthreads();
    int warp = (blockIdx.x * blockDim.x + threadIdx.x) >> 5;
    int lane = threadIdx.x & 31;
    int nwarps = (gridDim.x * blockDim.x) >> 5;
    for (int n = warp; n < NB; n += nwarps) {
        float h0 = h[(size_t)n * 64 + lane];
        float h1 = h[(size_t)n * 64 + 32 + lane];
        float d0 = 0, d1 = 0, d2 = 0, s0 = 0, s1 = 0, s2 = 0;
#pragma unroll
        for (int c = 0; c < 64; c++) {
            float hc = __shfl_sync(0xffffffffu, (c < 32) ? h0 : h1, c & 31);
            const float* wd = &Wd[c * 96 + lane];
            const float* ws = &Ws[c * 96 + lane];
            d0 = fmaf(hc, wd[0], d0);  d1 = fmaf(hc, wd[32], d1);  d2 = fmaf(hc, wd[64], d2);
            s0 = fmaf(hc, ws[0], s0);  s1 = fmaf(hc, ws[32], s1);  s2 = fmaf(hc, ws[64], s2);
        }
        Pd[(size_t)n * 96 + lane] = d0; Pd[(size_t)n * 96 + lane + 32] = d1; Pd[(size_t)n * 96 + lane + 64] = d2;
        Ps[(size_t)n * 96 + lane] = s0; Ps[(size_t)n * 96 + lane + 32] = s1; Ps[(size_t)n * 96 + lane + 64] = s2;
    }
}

// ---------------- EdgeConv via HMMA: A = 16 messages x 96, B = W2^T split fp16 ----------------
// smem: W2h fp16[64][104] @0 (13312), W2l @13312 (13312), b2 @26624 (256),
//       per-warp A: [hi 16x104 | lo 16x104] fp16 @26880 + w*6656. Total 80128.
#define EC_W2L 13312
#define EC_B2  26624
#define EC_A   26880
#define EC_AW  6656
#define EC_SMEM (26880 + 8*6656)
__global__ void __launch_bounds__(256, 2) edgeconv_kernel(
    const float* __restrict__ Pd, const float* __restrict__ Ps,
    const float* __restrict__ b1, const float* __restrict__ w2,
    const float* __restrict__ b2, const int* __restrict__ nbr,
    unsigned* __restrict__ agg, int Nn) {
    extern __shared__ unsigned char sm[];
    const unsigned sbase = (unsigned)__cvta_generic_to_shared(sm);
    __half* W2h = (__half*)sm;
    __half* W2l = (__half*)(sm + EC_W2L);
    float*  sB2 = (float*)(sm + EC_B2);
    const int w = threadIdx.x >> 5, lane = threadIdx.x & 31;

    // W2 transpose + split: w2[hh*64+out] -> [out][hh]
    for (int idx = threadIdx.x; idx < 96 * 64; idx += 256) {
        int hh = idx >> 6, out = idx & 63;
        float v = w2[idx];
        __half hi = __float2half(v);
        W2h[out * 104 + hh] = hi;
        W2l[out * 104 + hh] = __float2half(v - __half2float(hi));
    }
    if (threadIdx.x < 64) sB2[threadIdx.x] = b2[threadIdx.x];

    const int gn = blockIdx.x * 8 + w;
    const int b = gn / Nn;
    __half* Ah = (__half*)(sm + EC_A + w * EC_AW);
    __half* Al = Ah + 16 * 104;

    const float* pdi_p = Pd + (size_t)gn * 96;
    const float* psi_p = Ps + (size_t)gn * 96;
    float pdi0 = pdi_p[lane], pdi1 = pdi_p[lane + 32], pdi2 = pdi_p[lane + 64];
    float psi0 = psi_p[lane], psi1 = psi_p[lane + 32], psi2 = psi_p[lane + 64];
    float b10 = b1[lane], b11 = b1[lane + 32], b12 = b1[lane + 64];

    int nk = (lane < 8) ? nbr[(size_t)gn * 8 + lane] : 0;

    // stage messages: row k = F_k, row 8+k = R_k; split fp16 hi/lo
#pragma unroll 1
    for (int k = 0; k < 8; k++) {
        int j = __shfl_sync(0xffffffffu, nk, k);
        size_t jg = (size_t)b * Nn + j;
        const float* pdj = Pd + jg * 96;
        const float* psj = Ps + jg * 96;
        float f0 = eluf(pdi0 + psj[lane] + b10);
        float f1 = eluf(pdi1 + psj[lane + 32] + b11);
        float f2 = eluf(pdi2 + psj[lane + 64] + b12);
        float r0 = eluf(pdj[lane] + psi0 + b10);
        float r1 = eluf(pdj[lane + 32] + psi1 + b11);
        float r2 = eluf(pdj[lane + 64] + psi2 + b12);
        __half hv;
        hv = __float2half(f0); Ah[k * 104 + lane]      = hv; Al[k * 104 + lane]      = __float2half(f0 - __half2float(hv));
        hv = __float2half(f1); Ah[k * 104 + lane + 32] = hv; Al[k * 104 + lane + 32] = __float2half(f1 - __half2float(hv));
        hv = __float2half(f2); Ah[k * 104 + lane + 64] = hv; Al[k * 104 + lane + 64] = __float2half(f2 - __half2float(hv));
        hv = __float2half(r0); Ah[(k + 8) * 104 + lane]      = hv; Al[(k + 8) * 104 + lane]      = __float2half(r0 - __half2float(hv));
        hv = __float2half(r1); Ah[(k + 8) * 104 + lane + 32] = hv; Al[(k + 8) * 104 + lane + 32] = __float2half(r1 - __half2float(hv));
        hv = __float2half(r2); Ah[(k + 8) * 104 + lane + 64] = hv; Al[(k + 8) * 104 + lane + 64] = __float2half(r2 - __half2float(hv));
    }
    __syncthreads();

    // MMA: 6 k-steps x 8 n-tiles x 3 terms
    const int sub = lane >> 3, l7 = lane & 7;
    const unsigned aA = sbase + EC_A + w * EC_AW
                      + (unsigned)((l7 + ((sub & 1) ? 8 : 0)) * 208 + ((sub >> 1) ? 16 : 0));
    const unsigned bB = sbase + (unsigned)(l7 * 208 + (((lane >> 3) & 1) ? 16 : 0));

    float acc[8][4];
#pragma unroll
    for (int t = 0; t < 8; t++)
#pragma unroll
        for (int e = 0; e < 4; e++) acc[t][e] = 0.f;

#pragma unroll 1
    for (int ks = 0; ks < 6; ks++) {
        unsigned ah[4], al[4];
        ldm4(ah, aA + ks * 32);
        ldm4(al, aA + 16 * 208 + ks * 32);
        unsigned bh = bB + ks * 32;
#pragma unroll
        for (int t = 0; t < 8; t++) {
            unsigned bhv[2], blv[2];
            ldm2(bhv, bh);
            ldm2(blv, bh + EC_W2L);
            mma16816h(acc[t], ah, bhv);
            mma16816h(acc[t], al, bhv);
            mma16816h(acc[t], ah, blv);
            bh += 8 * 208;
        }
    }

    // epilogue: rows 0-7 = fwd (reduce max over rows -> gn), rows 8-15 = rev -> jn[row-8]
    const int jrev = __shfl_sync(0xffffffffu, nk, lane >> 2);
    const size_t jg = (size_t)b * Nn + jrev;
    const int myt = lane >> 2;
#pragma unroll
    for (int t = 0; t < 8; t++) {
        int c0 = t * 8 + (lane & 3) * 2;
        float bb0 = sB2[c0], bb1v = sB2[c0 + 1];
        unsigned e0 = encf(eluf(acc[t][0] + bb0));
        unsigned e1 = encf(eluf(acc[t][1] + bb1v));
        e0 = max(e0, __shfl_xor_sync(0xffffffffu, e0, 4));
        e0 = max(e0, __shfl_xor_sync(0xffffffffu, e0, 8));
        e0 = max(e0, __shfl_xor_sync(0xffffffffu, e0, 16));
        e1 = max(e1, __shfl_xor_sync(0xffffffffu, e1, 4));
        e1 = max(e1, __shfl_xor_sync(0xffffffffu, e1, 8));
        e1 = max(e1, __shfl_xor_sync(0xffffffffu, e1, 16));
        if (myt == t) {
            atomicMax(agg + (size_t)gn * 64 + c0,     e0);
            atomicMax(agg + (size_t)gn * 64 + c0 + 1, e1);
        }
        atomicMax(agg + jg * 64 + c0,     encf(eluf(acc[t][2] + bb0)));
        atomicMax(agg + jg * 64 + c0 + 1, encf(eluf(acc[t][3] + bb1v)));
    }
}

// ---------------- decode + pairwise max pool + sq-norm ----------------
__global__ void pool_kernel(const unsigned* __restrict__ agg, float* __restrict__ h3,
                            float* __restrict__ x2b) {
    int w = (blockIdx.x * blockDim.x + threadIdx.x) >> 5;
    int lane = threadIdx.x & 31;
    int b = w / N2c;
    int i = w - b * N2c;
    size_t s0 = ((size_t)(b * N1c + 2 * i)) * 64;
    float ss = 0.f;
#pragma unroll
    for (int r = 0; r < 2; r++) {
        int c = lane + 32 * r;
        float v = fmaxf(decf(agg[s0 + c]), decf(agg[s0 + 64 + c]));
        h3[(size_t)w * 64 + c] = v;
        ss = fmaf(v, v, ss);
    }
    for (int o = 16; o > 0; o >>= 1) ss += __shfl_down_sync(0xffffffffu, ss, o);
    if (lane == 0) x2b[w] = ss;
}

// ---------------- global max pool + head MLP ----------------
__global__ void final_kernel(const unsigned* __restrict__ agg,
                             const float* __restrict__ w1, const float* __restrict__ bb1,
                             const float* __restrict__ w2, const float* __restrict__ bb2,
                             const float* __restrict__ w3, const float* __restrict__ bb3,
                             float* __restrict__ out) {
    __shared__ float red[256];
    __shared__ float gv[64], t1[64], t2[32];
    int b = blockIdx.x;
    int c = threadIdx.x & 63, grp = threadIdx.x >> 6;
    float m = -3e38f;
    for (int n = grp; n < N2c; n += 4)
        m = fmaxf(m, decf(agg[((size_t)(b * N2c + n)) * 64 + c]));
    red[threadIdx.x] = m;
    __syncthreads();
    if (threadIdx.x < 64) {
        m = fmaxf(fmaxf(red[threadIdx.x], red[threadIdx.x + 64]),
                  fmaxf(red[threadIdx.x + 128], red[threadIdx.x + 192]));
        gv[threadIdx.x] = m;
    }
    __syncthreads();
    if (threadIdx.x < 64) {
        float acc = bb1[threadIdx.x];
#pragma unroll
        for (int cc = 0; cc < 64; cc++) acc = fmaf(gv[cc], w1[cc * 64 + threadIdx.x], acc);
        t1[threadIdx.x] = eluf(acc);
    }
    __syncthreads();
    if (threadIdx.x < 32) {
        float acc = bb2[threadIdx.x];
#pragma unroll
        for (int cc = 0; cc < 64; cc++) acc = fmaf(t1[cc], w2[cc * 32 + threadIdx.x], acc);
        t2[threadIdx.x] = eluf(acc);
    }
    __syncthreads();
    if (threadIdx.x == 0) {
        float o0 = bb3[0], o1 = bb3[1];
#pragma unroll
        for (int cc = 0; cc < 32; cc++) {
            o0 = fmaf(t2[cc], w3[cc * 2 + 0], o0);
            o1 = fmaf(t2[cc], w3[cc * 2 + 1], o1);
        }
        float met = fmaxf(o0, 0.f) + log1pf(expf(-fabsf(o0)));
        float sig = 1.f / (1.f + expf(-o1));
        float phi = 3.14159265358979323846f * (2.f * sig - 1.f);
        out[b * 2 + 0] = met;
        out[b * 2 + 1] = phi;
    }
}

// ---------------- launch ----------------
extern "C" void kernel_launch(void* const* d_in, const int* in_sizes, int n_in,
                              void* d_out, int out_size) {
    const float* x      = (const float*)d_in[0];
    const float* nrm    = (const float*)d_in[1];
    const float* w_in1  = (const float*)d_in[2];
    const float* b_in1  = (const float*)d_in[3];
    const float* w_in2  = (const float*)d_in[4];
    const float* b_in2  = (const float*)d_in[5];
    const float* w_c1a  = (const float*)d_in[6];
    const float* b_c1a  = (const float*)d_in[7];
    const float* w_c1b  = (const float*)d_in[8];
    const float* b_c1b  = (const float*)d_in[9];
    const float* w_c2a  = (const float*)d_in[10];
    const float* b_c2a  = (const float*)d_in[11];
    const float* w_c2b  = (const float*)d_in[12];
    const float* b_c2b  = (const float*)d_in[13];
    const float* w_o1   = (const float*)d_in[14];
    const float* b_o1   = (const float*)d_in[15];
    const float* w_o2   = (const float*)d_in[16];
    const float* b_o2   = (const float*)d_in[17];
    const float* w_o3   = (const float*)d_in[18];
    const float* b_o3   = (const float*)d_in[19];
    float* out = (float*)d_out;

    float *h1, *x2a, *Pd1, *Ps1, *h3, *x2b, *Pd2, *Ps2, *pd1, *pd2;
    int *nbr1, *nbr2, *pi1, *pi2, *cand1, *cand2;
    unsigned *agg1, *agg2;
    __half *hq1, *hq2;
    cudaGetSymbolAddress((void**)&h1,   g_h1);
    cudaGetSymbolAddress((void**)&x2a,  g_x2a);
    cudaGetSymbolAddress((void**)&nbr1, g_nbr1);
    cudaGetSymbolAddress((void**)&Pd1,  g_Pd1);
    cudaGetSymbolAddress((void**)&Ps1,  g_Ps1);
    cudaGetSymbolAddress((void**)&agg1, g_agg1);
    cudaGetSymbolAddress((void**)&h3,   g_h3);
    cudaGetSymbolAddress((void**)&x2b,  g_x2b);
    cudaGetSymbolAddress((void**)&nbr2, g_nbr2);
    cudaGetSymbolAddress((void**)&Pd2,  g_Pd2);
    cudaGetSymbolAddress((void**)&Ps2,  g_Ps2);
    cudaGetSymbolAddress((void**)&agg2, g_agg2);
    cudaGetSymbolAddress((void**)&pd1,  g_pd1);
    cudaGetSymbolAddress((void**)&pi1,  g_pi1);
    cudaGetSymbolAddress((void**)&pd2,  g_pd2);
    cudaGetSymbolAddress((void**)&pi2,  g_pi2);
    cudaGetSymbolAddress((void**)&cand1, g_cand1);
    cudaGetSymbolAddress((void**)&cand2, g_cand2);
    cudaGetSymbolAddress((void**)&hq1,  g_hq1);
    cudaGetSymbolAddress((void**)&hq2,  g_hq2);

    cudaFuncSetAttribute(knn_screen_kernel<N1c>, cudaFuncAttributeMaxDynamicSharedMemorySize, KNN_SMEM);
    cudaFuncSetAttribute(knn_screen_kernel<N2c>, cudaFuncAttributeMaxDynamicSharedMemorySize, KNN_SMEM);
    cudaFuncSetAttribute(edgeconv_kernel, cudaFuncAttributeMaxDynamicSharedMemorySize, EC_SMEM);

    zero2_kernel<<<1024, 256>>>(agg1, Bc * N1c * Hc, agg2, Bc * N2c * Hc);
    input_mlp_kernel<<<(Bc * N1c) / 128, 128>>>(x, nrm, w_in1, b_in1, w_in2, b_in2, h1, x2a);
    half_kernel<<<(Bc * N1c * Hc + 255) / 256, 256>>>(h1, hq1, Bc * N1c * Hc);
    // index 3 <-- ncu capture slot
    knn_screen_kernel<N1c><<<dim3(N1c / 64, CH, Bc), 128, KNN_SMEM>>>(hq1, x2a, pd1, pi1);
    knn_sel_kernel<<<(Bc * N1c + 255) / 256, 256>>>(pd1, pi1, cand1, Bc * N1c);
    knn_rescore_kernel<<<(Bc * N1c) / 8, 128>>>(h1, x2a, cand1, nbr1, N1c);
    proj_kernel<<<(Bc * N1c) / 8, 256>>>(h1, w_c1a, Pd1, Ps1, Bc * N1c);
    edgeconv_kernel<<<(Bc * N1c) / 8, 256, EC_SMEM>>>(Pd1, Ps1, b_c1a, w_c1b, b_c1b, nbr1, agg1, N1c);

    pool_kernel<<<(Bc * N2c) / 8, 256>>>(agg1, h3, x2b);
    half_kernel<<<(Bc * N2c * Hc + 255) / 256, 256>>>(h3, hq2, Bc * N2c * Hc);

    knn_screen_kernel<N2c><<<dim3(N2c / 64, CH, Bc), 128, KNN_SMEM>>>(hq2, x2b, pd2, pi2);
    knn_sel_kernel<<<(Bc * N2c + 255) / 256, 256>>>(pd2, pi2, cand2, Bc * N2c);
    knn_rescore_kernel<<<(Bc * N2c) / 8, 128>>>(h3, x2b, cand2, nbr2, N2c);
    proj_kernel<<<(Bc * N2c) / 8, 256>>>(h3, w_c2a, Pd2, Ps2, Bc * N2c);
    edgeconv_kernel<<<(Bc * N2c) / 8, 256, EC_SMEM>>>(Pd2, Ps2, b_c2a, w_c2b, b_c2b, nbr2, agg2, N2c);

    final_kernel<<<Bc, 256>>>(agg2, w_o1, b_o1, w_o2, b_o2, w_o3, b_o3, out);
}